// round 1
// baseline (speedup 1.0000x reference)
#include <cuda_runtime.h>
#include <math.h>

#define BATCH  2
#define SEQ    2047
#define NQ     2048
#define CDIM   1024
#define NHEAD  16
#define DHEAD  64
#define QT_TILES 32   // NQ / 64

// ---------------- scratch (device globals: no allocations allowed) ----------
__device__ float d_xg[(size_t)BATCH * NQ * CDIM];            // 16 MB: [g;x] concat
__device__ float d_qkvbuf[(size_t)BATCH * NQ * 3 * CDIM];    // 50 MB: (B,N,3,H,D)
__device__ float d_attbuf[(size_t)BATCH * NQ * CDIM];        // 16 MB: attention out

// ---------------- kernel 0: build xg = concat(global_token, x) --------------
__global__ void bwa_build_xg(const float* __restrict__ x,
                             const float* __restrict__ g)
{
    int i4 = blockIdx.x * blockDim.x + threadIdx.x;
    const int total = BATCH * NQ * (CDIM / 4);
    if (i4 >= total) return;
    int c4  = i4 & 255;          // CDIM/4 = 256
    int row = i4 >> 8;
    int n   = row & (NQ - 1);
    int b   = row >> 11;
    float4 v;
    if (n == 0) v = ((const float4*)g)[c4];
    else        v = ((const float4*)x)[((size_t)(b * SEQ + n - 1)) * 256 + c4];
    ((float4*)d_xg)[i4] = v;
}

// ---------------- generic 64x64 SGEMM: C = A @ W^T (+bias) ------------------
// A: [M, K] row-major (lda), W: [N, K] row-major, C: [M, N] (ldc)
// grid: (N/64, ceil(M/64), nbatch). 256 threads, 4x4 per thread.
template<bool HAS_BIAS>
__global__ void __launch_bounds__(256)
bwa_sgemm64x64(const float* __restrict__ A, long long strideAb, int lda,
               const float* __restrict__ W, int K,
               float* __restrict__ C, long long strideCb, int ldc,
               int M, const float* __restrict__ bias)
{
    __shared__ float As[16][64];
    __shared__ float Bs[16][64];

    const float* Ab = A + (long long)blockIdx.z * strideAb;
    float*       Cb = C + (long long)blockIdx.z * strideCb;
    const int m0  = blockIdx.y * 64;
    const int n0  = blockIdx.x * 64;
    const int tid = threadIdx.x;
    const int ty  = tid >> 4;
    const int tx  = tid & 15;
    const int lrow = tid >> 2;          // 0..63
    const int lk   = (tid & 3) << 2;    // 0,4,8,12

    float acc[4][4] = {};

    const int  mA  = m0 + lrow;
    const bool aok = (mA < M);
    const float* aptr = Ab + (long long)mA * lda + lk;
    const float* wptr = W + (long long)(n0 + lrow) * K + lk;

    for (int k0 = 0; k0 < K; k0 += 16) {
        float4 av = make_float4(0.f, 0.f, 0.f, 0.f);
        if (aok) av = *(const float4*)(aptr + k0);
        float4 wv = *(const float4*)(wptr + k0);
        As[lk + 0][lrow] = av.x; As[lk + 1][lrow] = av.y;
        As[lk + 2][lrow] = av.z; As[lk + 3][lrow] = av.w;
        Bs[lk + 0][lrow] = wv.x; Bs[lk + 1][lrow] = wv.y;
        Bs[lk + 2][lrow] = wv.z; Bs[lk + 3][lrow] = wv.w;
        __syncthreads();
        #pragma unroll
        for (int kk = 0; kk < 16; kk++) {
            float4 a4 = *(const float4*)&As[kk][ty << 2];
            float4 b4 = *(const float4*)&Bs[kk][tx << 2];
            float a[4] = {a4.x, a4.y, a4.z, a4.w};
            float b[4] = {b4.x, b4.y, b4.z, b4.w};
            #pragma unroll
            for (int i = 0; i < 4; i++)
                #pragma unroll
                for (int j = 0; j < 4; j++)
                    acc[i][j] += a[i] * b[j];
        }
        __syncthreads();
    }

    float4 bb = make_float4(0.f, 0.f, 0.f, 0.f);
    if (HAS_BIAS) bb = *(const float4*)(bias + n0 + (tx << 2));
    #pragma unroll
    for (int i = 0; i < 4; i++) {
        int m = m0 + (ty << 2) + i;
        if (m < M) {
            float4 r = make_float4(acc[i][0] + bb.x, acc[i][1] + bb.y,
                                   acc[i][2] + bb.z, acc[i][3] + bb.w);
            *(float4*)(Cb + (long long)m * ldc + n0 + (tx << 2)) = r;
        }
    }
}

// ---------------- kernel 2: block-causal flash attention --------------------
// One CTA = (b, h, query tile of 64). Key tiles 0..qt, NO masking needed
// since BLOCK_SIZE == tile size == 64.
__global__ void __launch_bounds__(256)
bwa_attn64(const float* __restrict__ qkv, float* __restrict__ att)
{
    __shared__ float Qs[64][64];   // [q][d], pre-scaled
    __shared__ float KP[64][64];   // Kt[d][key], later reused as P[q][key]
    __shared__ float Vs[64][64];   // [key][d]

    const int qt  = (QT_TILES - 1) - (int)blockIdx.x;  // big tiles first
    const int h   = blockIdx.y;
    const int b   = blockIdx.z;
    const int tid = threadIdx.x;
    const int ty  = tid >> 4;
    const int tx  = tid & 15;

    const long long base = (long long)b * NQ * 3 * CDIM;
    const int qoff = h * DHEAD;
    const int koff = CDIM + h * DHEAD;
    const int voff = 2 * CDIM + h * DHEAD;

    // load Q tile, fold in softmax scale (1/sqrt(64) = 0.125)
    {
        const int row = tid >> 2;
        const int d0  = (tid & 3) << 4;
        const float* src = qkv + base + (long long)(qt * 64 + row) * (3 * CDIM) + qoff + d0;
        #pragma unroll
        for (int i = 0; i < 4; i++) {
            float4 v = *(const float4*)(src + 4 * i);
            v.x *= 0.125f; v.y *= 0.125f; v.z *= 0.125f; v.w *= 0.125f;
            *(float4*)&Qs[row][d0 + 4 * i] = v;
        }
    }

    float mrow[4], lsum[4], o[4][4];
    #pragma unroll
    for (int i = 0; i < 4; i++) {
        mrow[i] = -1e30f; lsum[i] = 0.f;
        #pragma unroll
        for (int j = 0; j < 4; j++) o[i][j] = 0.f;
    }

    for (int kt = 0; kt <= qt; kt++) {
        __syncthreads();   // prior iteration done reading KP/Vs
        // K tile, transposed into smem: KP[d][key] (conflict-free writes: bank = key%32)
        {
            const int key = tid & 63;
            const int d0  = (tid >> 6) << 4;
            const float* src = qkv + base + (long long)(kt * 64 + key) * (3 * CDIM) + koff + d0;
            #pragma unroll
            for (int i = 0; i < 4; i++) {
                float4 v = *(const float4*)(src + 4 * i);
                KP[d0 + 4 * i + 0][key] = v.x;
                KP[d0 + 4 * i + 1][key] = v.y;
                KP[d0 + 4 * i + 2][key] = v.z;
                KP[d0 + 4 * i + 3][key] = v.w;
            }
        }
        // V tile, natural layout [key][d]
        {
            const int row = tid >> 2;
            const int d0  = (tid & 3) << 4;
            const float* src = qkv + base + (long long)(kt * 64 + row) * (3 * CDIM) + voff + d0;
            #pragma unroll
            for (int i = 0; i < 4; i++)
                *(float4*)&Vs[row][d0 + 4 * i] = *(const float4*)(src + 4 * i);
        }
        __syncthreads();

        // S = (Q*scale) @ K^T, 4x4 fragment per thread
        float s[4][4] = {};
        #pragma unroll
        for (int d = 0; d < 64; d += 4) {
            float a[4][4], kk_[4][4];
            #pragma unroll
            for (int i = 0; i < 4; i++) {
                float4 v = *(const float4*)&Qs[(ty << 2) + i][d];
                a[i][0] = v.x; a[i][1] = v.y; a[i][2] = v.z; a[i][3] = v.w;
            }
            #pragma unroll
            for (int k = 0; k < 4; k++) {
                float4 v = *(const float4*)&KP[d + k][tx << 2];
                kk_[k][0] = v.x; kk_[k][1] = v.y; kk_[k][2] = v.z; kk_[k][3] = v.w;
            }
            #pragma unroll
            for (int i = 0; i < 4; i++)
                #pragma unroll
                for (int j = 0; j < 4; j++)
                    #pragma unroll
                    for (int k = 0; k < 4; k++)
                        s[i][j] += a[i][k] * kk_[k][j];
        }

        // online softmax (row group = 16 lanes sharing ty, within one warp half)
        float p[4][4];
        #pragma unroll
        for (int i = 0; i < 4; i++) {
            float rm = fmaxf(fmaxf(s[i][0], s[i][1]), fmaxf(s[i][2], s[i][3]));
            #pragma unroll
            for (int off = 8; off >= 1; off >>= 1)
                rm = fmaxf(rm, __shfl_xor_sync(0xffffffffu, rm, off));
            float mnew  = fmaxf(mrow[i], rm);
            float alpha = __expf(mrow[i] - mnew);
            mrow[i] = mnew;
            float rs = 0.f;
            #pragma unroll
            for (int j = 0; j < 4; j++) { p[i][j] = __expf(s[i][j] - mnew); rs += p[i][j]; }
            #pragma unroll
            for (int off = 8; off >= 1; off >>= 1)
                rs += __shfl_xor_sync(0xffffffffu, rs, off);
            lsum[i] = lsum[i] * alpha + rs;
            #pragma unroll
            for (int j = 0; j < 4; j++) o[i][j] *= alpha;
        }

        __syncthreads();   // everyone done reading Kt -> reuse as P
        #pragma unroll
        for (int i = 0; i < 4; i++)
            *(float4*)&KP[(ty << 2) + i][tx << 2] =
                make_float4(p[i][0], p[i][1], p[i][2], p[i][3]);
        __syncthreads();

        // O += P @ V
        #pragma unroll
        for (int k = 0; k < 64; k += 4) {
            float pp[4][4], vv[4][4];
            #pragma unroll
            for (int i = 0; i < 4; i++) {
                float4 v = *(const float4*)&KP[(ty << 2) + i][k];
                pp[i][0] = v.x; pp[i][1] = v.y; pp[i][2] = v.z; pp[i][3] = v.w;
            }
            #pragma unroll
            for (int kk = 0; kk < 4; kk++) {
                float4 v = *(const float4*)&Vs[k + kk][tx << 2];
                vv[kk][0] = v.x; vv[kk][1] = v.y; vv[kk][2] = v.z; vv[kk][3] = v.w;
            }
            #pragma unroll
            for (int i = 0; i < 4; i++)
                #pragma unroll
                for (int j = 0; j < 4; j++)
                    #pragma unroll
                    for (int kk = 0; kk < 4; kk++)
                        o[i][j] += pp[i][kk] * vv[kk][j];
        }
    }

    // epilogue: normalize, write att[b][q][h*64 + d]
    #pragma unroll
    for (int i = 0; i < 4; i++) {
        float inv = 1.0f / lsum[i];
        float4 v = make_float4(o[i][0] * inv, o[i][1] * inv,
                               o[i][2] * inv, o[i][3] * inv);
        long long row = (long long)b * NQ + qt * 64 + (ty << 2) + i;
        *(float4*)(att + row * CDIM + h * DHEAD + (tx << 2)) = v;
    }
}

// ---------------- launch ----------------------------------------------------
extern "C" void kernel_launch(void* const* d_in, const int* in_sizes, int n_in,
                              void* d_out, int out_size)
{
    const float* x      = (const float*)d_in[0];
    const float* g      = (const float*)d_in[1];
    const float* qkv_w  = (const float*)d_in[2];
    const float* proj_w = (const float*)d_in[3];
    const float* proj_b = (const float*)d_in[4];
    float* out = (float*)d_out;

    float *xg, *qkvbuf, *attbuf;
    cudaGetSymbolAddress((void**)&xg,     d_xg);
    cudaGetSymbolAddress((void**)&qkvbuf, d_qkvbuf);
    cudaGetSymbolAddress((void**)&attbuf, d_attbuf);

    // 1) concat global token + x
    {
        int total4 = BATCH * NQ * (CDIM / 4);
        bwa_build_xg<<<(total4 + 255) / 256, 256>>>(x, g);
    }
    // 2) QKV GEMM: (B*N, C) @ (3C, C)^T -> (B*N, 3C)
    {
        dim3 grid(3 * CDIM / 64, BATCH * NQ / 64, 1);
        bwa_sgemm64x64<false><<<grid, 256>>>(xg, 0LL, CDIM,
                                             qkv_w, CDIM,
                                             qkvbuf, 0LL, 3 * CDIM,
                                             BATCH * NQ, nullptr);
    }
    // 3) block-causal flash attention
    {
        dim3 grid(QT_TILES, NHEAD, BATCH);
        bwa_attn64<<<grid, 256>>>(qkvbuf, attbuf);
    }
    // 4) output projection (drop global token row): per batch M=2047
    {
        dim3 grid(CDIM / 64, (SEQ + 63) / 64, BATCH);
        bwa_sgemm64x64<true><<<grid, 256>>>(attbuf + CDIM,
                                            (long long)NQ * CDIM, CDIM,
                                            proj_w, CDIM,
                                            out, (long long)SEQ * CDIM, CDIM,
                                            SEQ, proj_b);
    }
}

// round 3
// speedup vs baseline: 1.8435x; 1.8435x over previous
#include <cuda_runtime.h>
#include <cstdint>
#include <math.h>

#define BATCH  2
#define SEQ    2047
#define NQ     2048
#define CDIM   1024
#define NHEAD  16
#define DHEAD  64
#define QT_TILES 32   // NQ / 64

// ---------------- scratch (device globals: no allocations allowed) ----------
__device__ float d_xg[(size_t)BATCH * NQ * CDIM];            // 16 MB: [g;x] concat
__device__ float d_qkvbuf[(size_t)BATCH * NQ * 3 * CDIM];    // 50 MB: (B,N,3,H,D)
__device__ float d_attbuf[(size_t)BATCH * NQ * CDIM];        // 16 MB: attention out

// ======================= helpers ========================
__device__ __forceinline__ uint32_t smem_u32(const void* p) {
    uint32_t a;
    asm("{ .reg .u64 t; cvta.to.shared.u64 t, %1; cvt.u32.u64 %0, t; }"
        : "=r"(a) : "l"(p));
    return a;
}
__device__ __forceinline__ uint32_t f2tf32(uint32_t bits) {
    uint32_t r;
    asm("cvt.rna.tf32.f32 %0, %1;" : "=r"(r) : "f"(__uint_as_float(bits)));
    return r;
}
__device__ __forceinline__ void ldsm_x4(uint32_t& r0, uint32_t& r1,
                                        uint32_t& r2, uint32_t& r3, uint32_t addr) {
    asm volatile("ldmatrix.sync.aligned.m8n8.x4.shared.b16 {%0,%1,%2,%3}, [%4];"
                 : "=r"(r0), "=r"(r1), "=r"(r2), "=r"(r3) : "r"(addr));
}
__device__ __forceinline__ void mma_tf32(float* c, const uint32_t* a,
                                         uint32_t b0, uint32_t b1) {
    asm volatile(
        "mma.sync.aligned.m16n8k8.row.col.f32.tf32.tf32.f32 "
        "{%0,%1,%2,%3}, {%4,%5,%6,%7}, {%8,%9}, {%0,%1,%2,%3};"
        : "+f"(c[0]), "+f"(c[1]), "+f"(c[2]), "+f"(c[3])
        : "r"(a[0]), "r"(a[1]), "r"(a[2]), "r"(a[3]), "r"(b0), "r"(b1));
}
#define CP_ASYNC16(dst, src) \
    asm volatile("cp.async.cg.shared.global [%0], [%1], 16;" \
                 :: "r"(dst), "l"(src) : "memory")
#define CP_COMMIT()  asm volatile("cp.async.commit_group;" ::: "memory")
#define CP_WAIT1()   asm volatile("cp.async.wait_group 1;" ::: "memory")

__device__ __forceinline__ uint32_t swz(uint32_t off) {  // SW128
    return off ^ ((off >> 3) & 0x70);
}

// ---------------- kernel 0: build xg = concat(global_token, x) --------------
__global__ void bwa_build_xg(const float* __restrict__ x,
                             const float* __restrict__ g)
{
    int i4 = blockIdx.x * blockDim.x + threadIdx.x;
    const int total = BATCH * NQ * (CDIM / 4);
    if (i4 >= total) return;
    int c4  = i4 & 255;          // CDIM/4 = 256
    int row = i4 >> 8;
    int n   = row & (NQ - 1);
    int b   = row >> 11;
    float4 v;
    if (n == 0) v = ((const float4*)g)[c4];
    else        v = ((const float4*)x)[((size_t)(b * SEQ + n - 1)) * 256 + c4];
    ((float4*)d_xg)[i4] = v;
}

// ============ tf32 mma.sync GEMM: C = A @ W^T (+bias/epilogue) ==============
// A: [M, K] row-major, W: [Nn, K] row-major. CTA tile 128x128, K chunks of 32.
// 3-stage cp.async pipeline, SW128-swizzled smem, ldmatrix fragment loads.
// EPI=0: C[row*Nn + col] = acc
// EPI=1: row -> (b = row>>11, n = row&2047); skip n==0;
//        C[(b*2047 + n - 1)*Nn + col] = acc + bias[col]
#define GSTAGES 3
#define GSTAGE_BYTES 32768                         // A 16KB + B 16KB
#define GEMM_SMEM_TOTAL (GSTAGES * GSTAGE_BYTES)   // 96 KB

template<int EPI>
__global__ void __launch_bounds__(256)
bwa_mma_gemm(const float* __restrict__ A, const float* __restrict__ W,
             float* __restrict__ C, int Nn, int K,
             const float* __restrict__ bias)
{
    extern __shared__ __align__(1024) char smem[];
    const uint32_t sb = smem_u32(smem);
    const int tid  = threadIdx.x;
    const int wid  = tid >> 5;
    const int lane = tid & 31;
    const int wm   = wid >> 1;       // 0..3 -> m offset 32*wm
    const int wn   = wid & 1;        // 0..1 -> n offset 64*wn
    const int m0   = blockIdx.y * 128;
    const int n0   = blockIdx.x * 128;

    const float* Abase = A + (size_t)m0 * K;
    const float* Wbase = W + (size_t)n0 * K;

    // per-thread cp.async source/dst precompute: 8 x 16B per thread per stage
    // i = tid + 256*j ; row = i>>3 (0..127), c16 = i&7
    uint32_t dstoff[4];
    const float* srcA[4];
    const float* srcW[4];
    #pragma unroll
    for (int j = 0; j < 4; j++) {
        int i   = tid + 256 * j;
        int row = i >> 3;
        int c   = i & 7;
        dstoff[j] = swz((uint32_t)(row * 128 + c * 16));
        srcA[j] = Abase + (size_t)row * K + c * 4;
        srcW[j] = Wbase + (size_t)row * K + c * 4;
    }

    const int nch = K >> 5;   // K/32
    // prologue: fill stages 0,1 with chunks 0,1
    #pragma unroll
    for (int pc = 0; pc < 2; pc++) {
        uint32_t sA = sb + pc * GSTAGE_BYTES;
        uint32_t sB = sA + 16384;
        #pragma unroll
        for (int j = 0; j < 4; j++) {
            CP_ASYNC16(sA + dstoff[j], srcA[j] + pc * 32);
            CP_ASYNC16(sB + dstoff[j], srcW[j] + pc * 32);
        }
        CP_COMMIT();
    }

    float acc[2][8][4];
    #pragma unroll
    for (int mt = 0; mt < 2; mt++)
        #pragma unroll
        for (int j = 0; j < 8; j++)
            #pragma unroll
            for (int q = 0; q < 4; q++) acc[mt][j][q] = 0.f;

    // ldmatrix address pieces (within a stage): row = base + (lane&15),
    // colByte = ks*32 + ((lane>>4)<<4)
    const uint32_t lrow = (uint32_t)(lane & 15);
    const uint32_t lcol = (uint32_t)((lane >> 4) << 4);

    for (int kc = 0; kc < nch; kc++) {
        CP_WAIT1();
        __syncthreads();

        const uint32_t sA = sb + (kc % GSTAGES) * GSTAGE_BYTES;
        const uint32_t sB = sA + 16384;

        #pragma unroll
        for (int ks = 0; ks < 4; ks++) {
            const uint32_t cb = (uint32_t)(ks * 32) + lcol;
            // A fragments: two m16 tiles
            uint32_t a[2][4];
            #pragma unroll
            for (int mt = 0; mt < 2; mt++) {
                uint32_t row = (uint32_t)(wm * 32 + mt * 16) + lrow;
                uint32_t ad = sA + swz(row * 128 + cb);
                ldsm_x4(a[mt][0], a[mt][1], a[mt][2], a[mt][3], ad);
                #pragma unroll
                for (int q = 0; q < 4; q++) a[mt][q] = f2tf32(a[mt][q]);
            }
            // B fragments: four n16 tiles (covers n64)
            uint32_t br[4][4];
            #pragma unroll
            for (int bt = 0; bt < 4; bt++) {
                uint32_t row = (uint32_t)(wn * 64 + bt * 16) + lrow;
                uint32_t bd = sB + swz(row * 128 + cb);
                ldsm_x4(br[bt][0], br[bt][1], br[bt][2], br[bt][3], bd);
                #pragma unroll
                for (int q = 0; q < 4; q++) br[bt][q] = f2tf32(br[bt][q]);
            }
            #pragma unroll
            for (int mt = 0; mt < 2; mt++)
                #pragma unroll
                for (int j = 0; j < 8; j++) {
                    uint32_t b0 = br[j >> 1][(j & 1)];
                    uint32_t b1 = br[j >> 1][2 + (j & 1)];
                    mma_tf32(acc[mt][j], a[mt], b0, b1);
                }
        }

        // fill chunk kc+2 into stage (kc+2)%3 (stage of compute kc-1: safe,
        // the __syncthreads above ordered all warps past compute kc-1)
        if (kc + 2 < nch) {
            uint32_t fA = sb + ((kc + 2) % GSTAGES) * GSTAGE_BYTES;
            uint32_t fB = fA + 16384;
            #pragma unroll
            for (int j = 0; j < 4; j++) {
                CP_ASYNC16(fA + dstoff[j], srcA[j] + (kc + 2) * 32);
                CP_ASYNC16(fB + dstoff[j], srcW[j] + (kc + 2) * 32);
            }
        }
        CP_COMMIT();
    }

    // -------- epilogue --------
    const int lrow4 = lane >> 2;          // 0..7
    const int lcol2 = (lane & 3) * 2;
    #pragma unroll
    for (int mt = 0; mt < 2; mt++) {
        const int rbase = m0 + wm * 32 + mt * 16 + lrow4;
        #pragma unroll
        for (int j = 0; j < 8; j++) {
            const int col = n0 + wn * 64 + j * 8 + lcol2;
            if (EPI == 0) {
                float* p0 = C + (size_t)rbase * Nn + col;
                float* p1 = C + (size_t)(rbase + 8) * Nn + col;
                *(float2*)p0 = make_float2(acc[mt][j][0], acc[mt][j][1]);
                *(float2*)p1 = make_float2(acc[mt][j][2], acc[mt][j][3]);
            } else {
                float2 bb = *(const float2*)(bias + col);
                int n0r = rbase & (NQ - 1), b0r = rbase >> 11;
                if (n0r > 0) {
                    float* p = C + (size_t)(b0r * SEQ + n0r - 1) * Nn + col;
                    *(float2*)p = make_float2(acc[mt][j][0] + bb.x,
                                              acc[mt][j][1] + bb.y);
                }
                int r1 = rbase + 8;
                int n1r = r1 & (NQ - 1), b1r = r1 >> 11;
                if (n1r > 0) {
                    float* p = C + (size_t)(b1r * SEQ + n1r - 1) * Nn + col;
                    *(float2*)p = make_float2(acc[mt][j][2] + bb.x,
                                              acc[mt][j][3] + bb.y);
                }
            }
        }
    }
}

// ---------------- kernel 2: block-causal flash attention --------------------
__global__ void __launch_bounds__(256)
bwa_attn64(const float* __restrict__ qkv, float* __restrict__ att)
{
    __shared__ float Qs[64][64];   // [q][d], pre-scaled
    __shared__ float KP[64][64];   // Kt[d][key], later reused as P[q][key]
    __shared__ float Vs[64][64];   // [key][d]

    const int qt  = (QT_TILES - 1) - (int)blockIdx.x;  // big tiles first
    const int h   = blockIdx.y;
    const int b   = blockIdx.z;
    const int tid = threadIdx.x;
    const int ty  = tid >> 4;
    const int tx  = tid & 15;

    const long long base = (long long)b * NQ * 3 * CDIM;
    const int qoff = h * DHEAD;
    const int koff = CDIM + h * DHEAD;
    const int voff = 2 * CDIM + h * DHEAD;

    {
        const int row = tid >> 2;
        const int d0  = (tid & 3) << 4;
        const float* src = qkv + base + (long long)(qt * 64 + row) * (3 * CDIM) + qoff + d0;
        #pragma unroll
        for (int i = 0; i < 4; i++) {
            float4 v = *(const float4*)(src + 4 * i);
            v.x *= 0.125f; v.y *= 0.125f; v.z *= 0.125f; v.w *= 0.125f;
            *(float4*)&Qs[row][d0 + 4 * i] = v;
        }
    }

    float mrow[4], lsum[4], o[4][4];
    #pragma unroll
    for (int i = 0; i < 4; i++) {
        mrow[i] = -1e30f; lsum[i] = 0.f;
        #pragma unroll
        for (int j = 0; j < 4; j++) o[i][j] = 0.f;
    }

    for (int kt = 0; kt <= qt; kt++) {
        __syncthreads();
        {
            const int key = tid & 63;
            const int d0  = (tid >> 6) << 4;
            const float* src = qkv + base + (long long)(kt * 64 + key) * (3 * CDIM) + koff + d0;
            #pragma unroll
            for (int i = 0; i < 4; i++) {
                float4 v = *(const float4*)(src + 4 * i);
                KP[d0 + 4 * i + 0][key] = v.x;
                KP[d0 + 4 * i + 1][key] = v.y;
                KP[d0 + 4 * i + 2][key] = v.z;
                KP[d0 + 4 * i + 3][key] = v.w;
            }
        }
        {
            const int row = tid >> 2;
            const int d0  = (tid & 3) << 4;
            const float* src = qkv + base + (long long)(kt * 64 + row) * (3 * CDIM) + voff + d0;
            #pragma unroll
            for (int i = 0; i < 4; i++)
                *(float4*)&Vs[row][d0 + 4 * i] = *(const float4*)(src + 4 * i);
        }
        __syncthreads();

        float s[4][4] = {};
        #pragma unroll
        for (int d = 0; d < 64; d += 4) {
            float a[4][4], kk_[4][4];
            #pragma unroll
            for (int i = 0; i < 4; i++) {
                float4 v = *(const float4*)&Qs[(ty << 2) + i][d];
                a[i][0] = v.x; a[i][1] = v.y; a[i][2] = v.z; a[i][3] = v.w;
            }
            #pragma unroll
            for (int k = 0; k < 4; k++) {
                float4 v = *(const float4*)&KP[d + k][tx << 2];
                kk_[k][0] = v.x; kk_[k][1] = v.y; kk_[k][2] = v.z; kk_[k][3] = v.w;
            }
            #pragma unroll
            for (int i = 0; i < 4; i++)
                #pragma unroll
                for (int j = 0; j < 4; j++)
                    #pragma unroll
                    for (int k = 0; k < 4; k++)
                        s[i][j] += a[i][k] * kk_[k][j];
        }

        float p[4][4];
        #pragma unroll
        for (int i = 0; i < 4; i++) {
            float rm = fmaxf(fmaxf(s[i][0], s[i][1]), fmaxf(s[i][2], s[i][3]));
            #pragma unroll
            for (int off = 8; off >= 1; off >>= 1)
                rm = fmaxf(rm, __shfl_xor_sync(0xffffffffu, rm, off));
            float mnew  = fmaxf(mrow[i], rm);
            float alpha = __expf(mrow[i] - mnew);
            mrow[i] = mnew;
            float rs = 0.f;
            #pragma unroll
            for (int j = 0; j < 4; j++) { p[i][j] = __expf(s[i][j] - mnew); rs += p[i][j]; }
            #pragma unroll
            for (int off = 8; off >= 1; off >>= 1)
                rs += __shfl_xor_sync(0xffffffffu, rs, off);
            lsum[i] = lsum[i] * alpha + rs;
            #pragma unroll
            for (int j = 0; j < 4; j++) o[i][j] *= alpha;
        }

        __syncthreads();
        #pragma unroll
        for (int i = 0; i < 4; i++)
            *(float4*)&KP[(ty << 2) + i][tx << 2] =
                make_float4(p[i][0], p[i][1], p[i][2], p[i][3]);
        __syncthreads();

        #pragma unroll
        for (int k = 0; k < 64; k += 4) {
            float pp[4][4], vv[4][4];
            #pragma unroll
            for (int i = 0; i < 4; i++) {
                float4 v = *(const float4*)&KP[(ty << 2) + i][k];
                pp[i][0] = v.x; pp[i][1] = v.y; pp[i][2] = v.z; pp[i][3] = v.w;
            }
            #pragma unroll
            for (int kk = 0; kk < 4; kk++) {
                float4 v = *(const float4*)&Vs[k + kk][tx << 2];
                vv[kk][0] = v.x; vv[kk][1] = v.y; vv[kk][2] = v.z; vv[kk][3] = v.w;
            }
            #pragma unroll
            for (int i = 0; i < 4; i++)
                #pragma unroll
                for (int j = 0; j < 4; j++)
                    #pragma unroll
                    for (int kk = 0; kk < 4; kk++)
                        o[i][j] += pp[i][kk] * vv[kk][j];
        }
    }

    #pragma unroll
    for (int i = 0; i < 4; i++) {
        float inv = 1.0f / lsum[i];
        float4 v = make_float4(o[i][0] * inv, o[i][1] * inv,
                               o[i][2] * inv, o[i][3] * inv);
        long long row = (long long)b * NQ + qt * 64 + (ty << 2) + i;
        *(float4*)(att + row * CDIM + h * DHEAD + (tx << 2)) = v;
    }
}

// ---------------- launch ----------------------------------------------------
extern "C" void kernel_launch(void* const* d_in, const int* in_sizes, int n_in,
                              void* d_out, int out_size)
{
    const float* x      = (const float*)d_in[0];
    const float* g      = (const float*)d_in[1];
    const float* qkv_w  = (const float*)d_in[2];
    const float* proj_w = (const float*)d_in[3];
    const float* proj_b = (const float*)d_in[4];
    float* out = (float*)d_out;

    float *xg, *qkvbuf, *attbuf;
    cudaGetSymbolAddress((void**)&xg,     d_xg);
    cudaGetSymbolAddress((void**)&qkvbuf, d_qkvbuf);
    cudaGetSymbolAddress((void**)&attbuf, d_attbuf);

    cudaFuncSetAttribute(bwa_mma_gemm<0>,
                         cudaFuncAttributeMaxDynamicSharedMemorySize, GEMM_SMEM_TOTAL);
    cudaFuncSetAttribute(bwa_mma_gemm<1>,
                         cudaFuncAttributeMaxDynamicSharedMemorySize, GEMM_SMEM_TOTAL);

    // 1) concat global token + x
    {
        int total4 = BATCH * NQ * (CDIM / 4);
        bwa_build_xg<<<(total4 + 255) / 256, 256>>>(x, g);
    }
    // 2) QKV GEMM (tf32 mma.sync): (4096, 1024) @ (3072, 1024)^T
    {
        dim3 grid(3 * CDIM / 128, (BATCH * NQ) / 128, 1);
        bwa_mma_gemm<0><<<grid, 256, GEMM_SMEM_TOTAL>>>(
            xg, qkv_w, qkvbuf, 3 * CDIM, CDIM, nullptr);
    }
    // 3) block-causal flash attention (fp32 SIMT)
    {
        dim3 grid(QT_TILES, NHEAD, BATCH);
        bwa_attn64<<<grid, 256>>>(qkvbuf, attbuf);
    }
    // 4) output projection (tf32 mma.sync) with fused concat-drop + bias
    {
        dim3 grid(CDIM / 128, (BATCH * NQ) / 128, 1);
        bwa_mma_gemm<1><<<grid, 256, GEMM_SMEM_TOTAL>>>(
            attbuf, proj_w, out, CDIM, CDIM, proj_b);
    }
}

// round 4
// speedup vs baseline: 3.3078x; 1.7943x over previous
#include <cuda_runtime.h>
#include <cstdint>
#include <math.h>

#define BATCH  2
#define SEQ    2047
#define NQ     2048
#define CDIM   1024
#define NHEAD  16
#define DHEAD  64
#define QT_TILES 32   // NQ / 64

// ---------------- scratch (device globals: no allocations allowed) ----------
__device__ float d_xg[(size_t)BATCH * NQ * CDIM];            // 16 MB: [g;x] concat
__device__ float d_qkvbuf[(size_t)BATCH * NQ * 3 * CDIM];    // 50 MB: (B,N,3,H,D)
__device__ float d_attbuf[(size_t)BATCH * NQ * CDIM];        // 16 MB: attention out

// ======================= helpers ========================
__device__ __forceinline__ uint32_t smem_u32(const void* p) {
    uint32_t a;
    asm("{ .reg .u64 t; cvta.to.shared.u64 t, %1; cvt.u32.u64 %0, t; }"
        : "=r"(a) : "l"(p));
    return a;
}
__device__ __forceinline__ uint32_t f2tf32(uint32_t bits) {
    uint32_t r;
    asm("cvt.rna.tf32.f32 %0, %1;" : "=r"(r) : "f"(__uint_as_float(bits)));
    return r;
}
__device__ __forceinline__ uint32_t f2tf32f(float x) {
    uint32_t r;
    asm("cvt.rna.tf32.f32 %0, %1;" : "=r"(r) : "f"(x));
    return r;
}
__device__ __forceinline__ float ex2(float x) {
    float r;
    asm("ex2.approx.ftz.f32 %0, %1;" : "=f"(r) : "f"(x));
    return r;
}
__device__ __forceinline__ void ldsm_x4(uint32_t& r0, uint32_t& r1,
                                        uint32_t& r2, uint32_t& r3, uint32_t addr) {
    asm volatile("ldmatrix.sync.aligned.m8n8.x4.shared.b16 {%0,%1,%2,%3}, [%4];"
                 : "=r"(r0), "=r"(r1), "=r"(r2), "=r"(r3) : "r"(addr));
}
__device__ __forceinline__ void mma_tf32(float* c, const uint32_t* a,
                                         uint32_t b0, uint32_t b1) {
    asm volatile(
        "mma.sync.aligned.m16n8k8.row.col.f32.tf32.tf32.f32 "
        "{%0,%1,%2,%3}, {%4,%5,%6,%7}, {%8,%9}, {%0,%1,%2,%3};"
        : "+f"(c[0]), "+f"(c[1]), "+f"(c[2]), "+f"(c[3])
        : "r"(a[0]), "r"(a[1]), "r"(a[2]), "r"(a[3]), "r"(b0), "r"(b1));
}
#define CP_ASYNC16(dst, src) \
    asm volatile("cp.async.cg.shared.global [%0], [%1], 16;" \
                 :: "r"(dst), "l"(src) : "memory")
#define CP_COMMIT()  asm volatile("cp.async.commit_group;" ::: "memory")
#define CP_WAIT1()   asm volatile("cp.async.wait_group 1;" ::: "memory")

__device__ __forceinline__ uint32_t swz(uint32_t off) {    // 128B-row tiles
    return off ^ ((off >> 3) & 0x70);
}
__device__ __forceinline__ uint32_t swz256(uint32_t off) { // 256B-row tiles
    return off ^ ((off >> 4) & 0x70);
}

#define ST_S4(addr, x0, x1, x2, x3) \
    asm volatile("st.shared.v4.b32 [%0], {%1,%2,%3,%4};" \
                 :: "r"(addr), "r"(x0), "r"(x1), "r"(x2), "r"(x3) : "memory")
#define ST_S2(addr, x0, x1) \
    asm volatile("st.shared.v2.b32 [%0], {%1,%2};" \
                 :: "r"(addr), "r"(x0), "r"(x1) : "memory")
#define ST_S1(addr, x0) \
    asm volatile("st.shared.b32 [%0], %1;" :: "r"(addr), "r"(x0) : "memory")

// ---------------- kernel 0: build xg = concat(global_token, x) --------------
__global__ void bwa_build_xg(const float* __restrict__ x,
                             const float* __restrict__ g)
{
    int i4 = blockIdx.x * blockDim.x + threadIdx.x;
    const int total = BATCH * NQ * (CDIM / 4);
    if (i4 >= total) return;
    int c4  = i4 & 255;
    int row = i4 >> 8;
    int n   = row & (NQ - 1);
    int b   = row >> 11;
    float4 v;
    if (n == 0) v = ((const float4*)g)[c4];
    else        v = ((const float4*)x)[((size_t)(b * SEQ + n - 1)) * 256 + c4];
    ((float4*)d_xg)[i4] = v;
}

// ============ tf32 mma.sync GEMM: C = A @ W^T (+bias/epilogue) ==============
#define GSTAGES 3
#define GSTAGE_BYTES 32768
#define GEMM_SMEM_TOTAL (GSTAGES * GSTAGE_BYTES)   // 96 KB

template<int EPI>
__global__ void __launch_bounds__(256)
bwa_mma_gemm(const float* __restrict__ A, const float* __restrict__ W,
             float* __restrict__ C, int Nn, int K,
             const float* __restrict__ bias)
{
    extern __shared__ __align__(1024) char smem[];
    const uint32_t sb = smem_u32(smem);
    const int tid  = threadIdx.x;
    const int wid  = tid >> 5;
    const int lane = tid & 31;
    const int wm   = wid >> 1;
    const int wn   = wid & 1;
    const int m0   = blockIdx.y * 128;
    const int n0   = blockIdx.x * 128;

    const float* Abase = A + (size_t)m0 * K;
    const float* Wbase = W + (size_t)n0 * K;

    uint32_t dstoff[4];
    const float* srcA[4];
    const float* srcW[4];
    #pragma unroll
    for (int j = 0; j < 4; j++) {
        int i   = tid + 256 * j;
        int row = i >> 3;
        int c   = i & 7;
        dstoff[j] = swz((uint32_t)(row * 128 + c * 16));
        srcA[j] = Abase + (size_t)row * K + c * 4;
        srcW[j] = Wbase + (size_t)row * K + c * 4;
    }

    const int nch = K >> 5;
    #pragma unroll
    for (int pc = 0; pc < 2; pc++) {
        uint32_t sA = sb + pc * GSTAGE_BYTES;
        uint32_t sB = sA + 16384;
        #pragma unroll
        for (int j = 0; j < 4; j++) {
            CP_ASYNC16(sA + dstoff[j], srcA[j] + pc * 32);
            CP_ASYNC16(sB + dstoff[j], srcW[j] + pc * 32);
        }
        CP_COMMIT();
    }

    float acc[2][8][4];
    #pragma unroll
    for (int mt = 0; mt < 2; mt++)
        #pragma unroll
        for (int j = 0; j < 8; j++)
            #pragma unroll
            for (int q = 0; q < 4; q++) acc[mt][j][q] = 0.f;

    const uint32_t lrow = (uint32_t)(lane & 15);
    const uint32_t lcol = (uint32_t)((lane >> 4) << 4);

    for (int kc = 0; kc < nch; kc++) {
        CP_WAIT1();
        __syncthreads();

        const uint32_t sA = sb + (kc % GSTAGES) * GSTAGE_BYTES;
        const uint32_t sB = sA + 16384;

        #pragma unroll
        for (int ks = 0; ks < 4; ks++) {
            const uint32_t cb = (uint32_t)(ks * 32) + lcol;
            uint32_t a[2][4];
            #pragma unroll
            for (int mt = 0; mt < 2; mt++) {
                uint32_t row = (uint32_t)(wm * 32 + mt * 16) + lrow;
                uint32_t ad = sA + swz(row * 128 + cb);
                ldsm_x4(a[mt][0], a[mt][1], a[mt][2], a[mt][3], ad);
                #pragma unroll
                for (int q = 0; q < 4; q++) a[mt][q] = f2tf32(a[mt][q]);
            }
            uint32_t br[4][4];
            #pragma unroll
            for (int bt = 0; bt < 4; bt++) {
                uint32_t row = (uint32_t)(wn * 64 + bt * 16) + lrow;
                uint32_t bd = sB + swz(row * 128 + cb);
                ldsm_x4(br[bt][0], br[bt][1], br[bt][2], br[bt][3], bd);
                #pragma unroll
                for (int q = 0; q < 4; q++) br[bt][q] = f2tf32(br[bt][q]);
            }
            #pragma unroll
            for (int mt = 0; mt < 2; mt++)
                #pragma unroll
                for (int j = 0; j < 8; j++) {
                    uint32_t b0 = br[j >> 1][(j & 1)];
                    uint32_t b1 = br[j >> 1][2 + (j & 1)];
                    mma_tf32(acc[mt][j], a[mt], b0, b1);
                }
        }

        if (kc + 2 < nch) {
            uint32_t fA = sb + ((kc + 2) % GSTAGES) * GSTAGE_BYTES;
            uint32_t fB = fA + 16384;
            #pragma unroll
            for (int j = 0; j < 4; j++) {
                CP_ASYNC16(fA + dstoff[j], srcA[j] + (kc + 2) * 32);
                CP_ASYNC16(fB + dstoff[j], srcW[j] + (kc + 2) * 32);
            }
        }
        CP_COMMIT();
    }

    const int lrow4 = lane >> 2;
    const int lcol2 = (lane & 3) * 2;
    #pragma unroll
    for (int mt = 0; mt < 2; mt++) {
        const int rbase = m0 + wm * 32 + mt * 16 + lrow4;
        #pragma unroll
        for (int j = 0; j < 8; j++) {
            const int col = n0 + wn * 64 + j * 8 + lcol2;
            if (EPI == 0) {
                float* p0 = C + (size_t)rbase * Nn + col;
                float* p1 = C + (size_t)(rbase + 8) * Nn + col;
                *(float2*)p0 = make_float2(acc[mt][j][0], acc[mt][j][1]);
                *(float2*)p1 = make_float2(acc[mt][j][2], acc[mt][j][3]);
            } else {
                float2 bb = *(const float2*)(bias + col);
                int n0r = rbase & (NQ - 1), b0r = rbase >> 11;
                if (n0r > 0) {
                    float* p = C + (size_t)(b0r * SEQ + n0r - 1) * Nn + col;
                    *(float2*)p = make_float2(acc[mt][j][0] + bb.x,
                                              acc[mt][j][1] + bb.y);
                }
                int r1 = rbase + 8;
                int n1r = r1 & (NQ - 1), b1r = r1 >> 11;
                if (n1r > 0) {
                    float* p = C + (size_t)(b1r * SEQ + n1r - 1) * Nn + col;
                    *(float2*)p = make_float2(acc[mt][j][2] + bb.x,
                                              acc[mt][j][3] + bb.y);
                }
            }
        }
    }
}

// ============ block-causal flash attention, tf32 mma.sync ===================
// CTA = (b, h, qt): 64 queries. 4 warps; warp w owns query rows 16w..16w+15.
// smem tiles 64x64 fp32(tf32 bits), 256B rows, swz256.
//   Qs [q][d] (scale*log2e folded), Ks [key][d], Vt [d][key], Ps [q][key].
#define ATT_SMEM_TOTAL 65536

__global__ void __launch_bounds__(128, 3)
bwa_attn_mma(const float* __restrict__ qkv, float* __restrict__ att)
{
    extern __shared__ __align__(1024) char smem[];
    const uint32_t sb = smem_u32(smem);
    const uint32_t Qs = sb;
    const uint32_t Ks = sb + 16384;
    const uint32_t Vt = sb + 32768;
    const uint32_t Ps = sb + 49152;

    const int tid  = threadIdx.x;
    const int w    = tid >> 5;
    const int lane = tid & 31;
    const int qt   = (QT_TILES - 1) - (int)blockIdx.x;  // big tiles first
    const int h    = blockIdx.y;
    const int b    = blockIdx.z;

    const long long base = (long long)b * NQ * 3 * CDIM;
    const float* qp = qkv + base + h * DHEAD;
    const float* kp = qkv + base + CDIM + h * DHEAD;
    const float* vp = qkv + base + 2 * CDIM + h * DHEAD;

    // ---- load Q tile: fold softmax scale * log2(e), cvt to tf32 ----
    const float QSC = 0.125f * 1.44269504f;
    #pragma unroll
    for (int j = 0; j < 8; j++) {
        int idx = tid + 128 * j;          // 1024 float4
        int row = idx >> 4, c4 = idx & 15;
        float4 v = *(const float4*)(qp + (long long)(qt * 64 + row) * (3 * CDIM) + c4 * 4);
        uint32_t x0 = f2tf32f(v.x * QSC), x1 = f2tf32f(v.y * QSC);
        uint32_t x2 = f2tf32f(v.z * QSC), x3 = f2tf32f(v.w * QSC);
        ST_S4(Qs + swz256((uint32_t)(row * 256 + c4 * 16)), x0, x1, x2, x3);
    }

    float o[8][4];
    #pragma unroll
    for (int nt = 0; nt < 8; nt++)
        #pragma unroll
        for (int q = 0; q < 4; q++) o[nt][q] = 0.f;
    float mrow[2] = { -1e30f, -1e30f };
    float lsum[2] = { 0.f, 0.f };

    const uint32_t lr = (uint32_t)(lane & 15);
    const uint32_t lc = (uint32_t)((lane >> 4) << 4);
    const uint32_t arow = (uint32_t)(16 * w) + lr;      // ldmatrix A row

    for (int kt = 0; kt <= qt; kt++) {
        __syncthreads();   // previous iteration finished reading Ks/Vt

        // ---- K tile [key][d] ----
        #pragma unroll
        for (int j = 0; j < 8; j++) {
            int idx = tid + 128 * j;
            int row = idx >> 4, c4 = idx & 15;
            float4 v = *(const float4*)(kp + (long long)(kt * 64 + row) * (3 * CDIM) + c4 * 4);
            ST_S4(Ks + swz256((uint32_t)(row * 256 + c4 * 16)),
                  f2tf32(__float_as_uint(v.x)), f2tf32(__float_as_uint(v.y)),
                  f2tf32(__float_as_uint(v.z)), f2tf32(__float_as_uint(v.w)));
        }
        // ---- V tile transposed -> Vt[d][key] ----
        {
            int key = tid >> 1;
            int db  = (tid & 1) * 32;
            const float* src = vp + (long long)(kt * 64 + key) * (3 * CDIM) + db;
            #pragma unroll
            for (int j = 0; j < 8; j++) {
                float4 v = *(const float4*)(src + 4 * j);
                int d0 = db + 4 * j;
                ST_S1(Vt + swz256((uint32_t)((d0 + 0) * 256 + key * 4)), f2tf32(__float_as_uint(v.x)));
                ST_S1(Vt + swz256((uint32_t)((d0 + 1) * 256 + key * 4)), f2tf32(__float_as_uint(v.y)));
                ST_S1(Vt + swz256((uint32_t)((d0 + 2) * 256 + key * 4)), f2tf32(__float_as_uint(v.z)));
                ST_S1(Vt + swz256((uint32_t)((d0 + 3) * 256 + key * 4)), f2tf32(__float_as_uint(v.w)));
            }
        }
        __syncthreads();

        // ---- S = Q @ K^T  (16 rows x 64 keys per warp) ----
        float s[8][4];
        #pragma unroll
        for (int nt = 0; nt < 8; nt++)
            #pragma unroll
            for (int q = 0; q < 4; q++) s[nt][q] = 0.f;

        #pragma unroll
        for (int ks = 0; ks < 8; ks++) {
            const uint32_t cb = (uint32_t)(32 * ks) + lc;
            uint32_t a[4];
            ldsm_x4(a[0], a[1], a[2], a[3], Qs + swz256(arow * 256 + cb));
            uint32_t br[4][4];
            #pragma unroll
            for (int bt = 0; bt < 4; bt++)
                ldsm_x4(br[bt][0], br[bt][1], br[bt][2], br[bt][3],
                        Ks + swz256(((uint32_t)(16 * bt) + lr) * 256 + cb));
            #pragma unroll
            for (int nt = 0; nt < 8; nt++)
                mma_tf32(s[nt], a, br[nt >> 1][nt & 1], br[nt >> 1][2 + (nt & 1)]);
        }

        // ---- online softmax (base-2 domain) ----
        float rm0 = -1e30f, rm1 = -1e30f;
        #pragma unroll
        for (int nt = 0; nt < 8; nt++) {
            rm0 = fmaxf(rm0, fmaxf(s[nt][0], s[nt][1]));
            rm1 = fmaxf(rm1, fmaxf(s[nt][2], s[nt][3]));
        }
        rm0 = fmaxf(rm0, __shfl_xor_sync(0xffffffffu, rm0, 1));
        rm0 = fmaxf(rm0, __shfl_xor_sync(0xffffffffu, rm0, 2));
        rm1 = fmaxf(rm1, __shfl_xor_sync(0xffffffffu, rm1, 1));
        rm1 = fmaxf(rm1, __shfl_xor_sync(0xffffffffu, rm1, 2));

        float mn0 = fmaxf(mrow[0], rm0), mn1 = fmaxf(mrow[1], rm1);
        float al0 = ex2(mrow[0] - mn0),  al1 = ex2(mrow[1] - mn1);
        mrow[0] = mn0; mrow[1] = mn1;

        float rs0 = 0.f, rs1 = 0.f;
        #pragma unroll
        for (int nt = 0; nt < 8; nt++) {
            s[nt][0] = ex2(s[nt][0] - mn0);
            s[nt][1] = ex2(s[nt][1] - mn0);
            s[nt][2] = ex2(s[nt][2] - mn1);
            s[nt][3] = ex2(s[nt][3] - mn1);
            rs0 += s[nt][0] + s[nt][1];
            rs1 += s[nt][2] + s[nt][3];
        }
        rs0 += __shfl_xor_sync(0xffffffffu, rs0, 1);
        rs0 += __shfl_xor_sync(0xffffffffu, rs0, 2);
        rs1 += __shfl_xor_sync(0xffffffffu, rs1, 1);
        rs1 += __shfl_xor_sync(0xffffffffu, rs1, 2);
        lsum[0] = lsum[0] * al0 + rs0;
        lsum[1] = lsum[1] * al1 + rs1;
        #pragma unroll
        for (int nt = 0; nt < 8; nt++) {
            o[nt][0] *= al0; o[nt][1] *= al0;
            o[nt][2] *= al1; o[nt][3] *= al1;
        }

        // ---- store P to warp-private smem rows (tf32) ----
        const uint32_t pr = (uint32_t)(16 * w + (lane >> 2));
        #pragma unroll
        for (int nt = 0; nt < 8; nt++) {
            uint32_t cbyte = (uint32_t)(32 * nt + 8 * (lane & 3));
            ST_S2(Ps + swz256(pr * 256 + cbyte), f2tf32f(s[nt][0]), f2tf32f(s[nt][1]));
            ST_S2(Ps + swz256((pr + 8) * 256 + cbyte), f2tf32f(s[nt][2]), f2tf32f(s[nt][3]));
        }
        __syncwarp();

        // ---- O += P @ V ----
        #pragma unroll
        for (int ks = 0; ks < 8; ks++) {
            const uint32_t cb = (uint32_t)(32 * ks) + lc;
            uint32_t a[4];
            ldsm_x4(a[0], a[1], a[2], a[3], Ps + swz256(arow * 256 + cb));
            uint32_t br[4][4];
            #pragma unroll
            for (int bt = 0; bt < 4; bt++)
                ldsm_x4(br[bt][0], br[bt][1], br[bt][2], br[bt][3],
                        Vt + swz256(((uint32_t)(16 * bt) + lr) * 256 + cb));
            #pragma unroll
            for (int nt = 0; nt < 8; nt++)
                mma_tf32(o[nt], a, br[nt >> 1][nt & 1], br[nt >> 1][2 + (nt & 1)]);
        }
        __syncwarp();
    }

    // ---- epilogue: normalize, write att[b][q][h*64 + d] ----
    float i0 = 1.f / lsum[0], i1 = 1.f / lsum[1];
    int r0 = qt * 64 + 16 * w + (lane >> 2);
    float* orow0 = att + ((long long)b * NQ + r0) * CDIM + h * DHEAD;
    float* orow1 = orow0 + 8 * CDIM;
    #pragma unroll
    for (int nt = 0; nt < 8; nt++) {
        int col = 8 * nt + 2 * (lane & 3);
        *(float2*)(orow0 + col) = make_float2(o[nt][0] * i0, o[nt][1] * i0);
        *(float2*)(orow1 + col) = make_float2(o[nt][2] * i1, o[nt][3] * i1);
    }
}

// ---------------- launch ----------------------------------------------------
extern "C" void kernel_launch(void* const* d_in, const int* in_sizes, int n_in,
                              void* d_out, int out_size)
{
    const float* x      = (const float*)d_in[0];
    const float* g      = (const float*)d_in[1];
    const float* qkv_w  = (const float*)d_in[2];
    const float* proj_w = (const float*)d_in[3];
    const float* proj_b = (const float*)d_in[4];
    float* out = (float*)d_out;

    float *xg, *qkvbuf, *attbuf;
    cudaGetSymbolAddress((void**)&xg,     d_xg);
    cudaGetSymbolAddress((void**)&qkvbuf, d_qkvbuf);
    cudaGetSymbolAddress((void**)&attbuf, d_attbuf);

    cudaFuncSetAttribute(bwa_mma_gemm<0>,
                         cudaFuncAttributeMaxDynamicSharedMemorySize, GEMM_SMEM_TOTAL);
    cudaFuncSetAttribute(bwa_mma_gemm<1>,
                         cudaFuncAttributeMaxDynamicSharedMemorySize, GEMM_SMEM_TOTAL);
    cudaFuncSetAttribute(bwa_attn_mma,
                         cudaFuncAttributeMaxDynamicSharedMemorySize, ATT_SMEM_TOTAL);

    // 1) concat global token + x
    {
        int total4 = BATCH * NQ * (CDIM / 4);
        bwa_build_xg<<<(total4 + 255) / 256, 256>>>(x, g);
    }
    // 2) QKV GEMM (tf32 mma.sync): (4096, 1024) @ (3072, 1024)^T
    {
        dim3 grid(3 * CDIM / 128, (BATCH * NQ) / 128, 1);
        bwa_mma_gemm<0><<<grid, 256, GEMM_SMEM_TOTAL>>>(
            xg, qkv_w, qkvbuf, 3 * CDIM, CDIM, nullptr);
    }
    // 3) block-causal flash attention (tf32 mma.sync)
    {
        dim3 grid(QT_TILES, NHEAD, BATCH);
        bwa_attn_mma<<<grid, 128, ATT_SMEM_TOTAL>>>(qkvbuf, attbuf);
    }
    // 4) output projection (tf32 mma.sync) with fused concat-drop + bias
    {
        dim3 grid(CDIM / 128, (BATCH * NQ) / 128, 1);
        bwa_mma_gemm<1><<<grid, 256, GEMM_SMEM_TOTAL>>>(
            attbuf, proj_w, out, CDIM, CDIM, proj_b);
    }
}

// round 6
// speedup vs baseline: 3.6656x; 1.1082x over previous
#include <cuda_runtime.h>
#include <cstdint>
#include <math.h>

#define BATCH  2
#define SEQ    2047
#define NQ     2048
#define CDIM   1024
#define NHEAD  16
#define DHEAD  64
#define QT_TILES 32   // NQ / 64

// ---------------- scratch (device globals: no allocations allowed) ----------
__device__ float d_xg[(size_t)BATCH * NQ * CDIM];            // tf32-rounded
__device__ float d_qkvbuf[(size_t)BATCH * NQ * 3 * CDIM];    // tf32-rounded
__device__ float d_attbuf[(size_t)BATCH * NQ * CDIM];        // tf32-rounded
__device__ float d_qkvw_tf[(size_t)3 * CDIM * CDIM];         // tf32-rounded weights
__device__ float d_projw_tf[(size_t)CDIM * CDIM];

// ======================= helpers ========================
__device__ __forceinline__ uint32_t smem_u32(const void* p) {
    uint32_t a;
    asm("{ .reg .u64 t; cvta.to.shared.u64 t, %1; cvt.u32.u64 %0, t; }"
        : "=r"(a) : "l"(p));
    return a;
}
__device__ __forceinline__ uint32_t f2tf32f(float x) {
    uint32_t r;
    asm("cvt.rna.tf32.f32 %0, %1;" : "=r"(r) : "f"(x));
    return r;
}
__device__ __forceinline__ float ex2(float x) {
    float r;
    asm("ex2.approx.ftz.f32 %0, %1;" : "=f"(r) : "f"(x));
    return r;
}
__device__ __forceinline__ void ldsm_x4(uint32_t& r0, uint32_t& r1,
                                        uint32_t& r2, uint32_t& r3, uint32_t addr) {
    asm volatile("ldmatrix.sync.aligned.m8n8.x4.shared.b16 {%0,%1,%2,%3}, [%4];"
                 : "=r"(r0), "=r"(r1), "=r"(r2), "=r"(r3) : "r"(addr));
}
__device__ __forceinline__ void mma_tf32(float* c, const uint32_t* a,
                                         uint32_t b0, uint32_t b1) {
    asm volatile(
        "mma.sync.aligned.m16n8k8.row.col.f32.tf32.tf32.f32 "
        "{%0,%1,%2,%3}, {%4,%5,%6,%7}, {%8,%9}, {%0,%1,%2,%3};"
        : "+f"(c[0]), "+f"(c[1]), "+f"(c[2]), "+f"(c[3])
        : "r"(a[0]), "r"(a[1]), "r"(a[2]), "r"(a[3]), "r"(b0), "r"(b1));
}
#define CP_ASYNC16(dst, src) \
    asm volatile("cp.async.cg.shared.global [%0], [%1], 16;" \
                 :: "r"(dst), "l"(src) : "memory")
#define CP_COMMIT()  asm volatile("cp.async.commit_group;" ::: "memory")
#define CP_WAIT1()   asm volatile("cp.async.wait_group 1;" ::: "memory")
#define CP_WAIT0()   asm volatile("cp.async.wait_group 0;" ::: "memory")

__device__ __forceinline__ uint32_t swz(uint32_t off) {    // 128B-row tiles
    return off ^ ((off >> 3) & 0x70);
}
__device__ __forceinline__ uint32_t swz256(uint32_t off) { // 256B-row tiles
    return off ^ ((off >> 4) & 0x70);
}

#define ST_S4(addr, x0, x1, x2, x3) \
    asm volatile("st.shared.v4.b32 [%0], {%1,%2,%3,%4};" \
                 :: "r"(addr), "r"(x0), "r"(x1), "r"(x2), "r"(x3) : "memory")
#define ST_S2(addr, x0, x1) \
    asm volatile("st.shared.v2.b32 [%0], {%1,%2};" \
                 :: "r"(addr), "r"(x0), "r"(x1) : "memory")
#define ST_S1(addr, x0) \
    asm volatile("st.shared.b32 [%0], %1;" :: "r"(addr), "r"(x0) : "memory")

// ---------------- kernel: elementwise tf32 rounding -------------------------
__global__ void bwa_round_tf32(const float* __restrict__ src,
                               float* __restrict__ dst, int n4)
{
    int i = blockIdx.x * blockDim.x + threadIdx.x;
    if (i >= n4) return;
    float4 v = ((const float4*)src)[i];
    float4 r;
    r.x = __uint_as_float(f2tf32f(v.x));
    r.y = __uint_as_float(f2tf32f(v.y));
    r.z = __uint_as_float(f2tf32f(v.z));
    r.w = __uint_as_float(f2tf32f(v.w));
    ((float4*)dst)[i] = r;
}

// ---------------- kernel 0: build xg = concat(g, x), tf32-rounded -----------
__global__ void bwa_build_xg(const float* __restrict__ x,
                             const float* __restrict__ g)
{
    int i4 = blockIdx.x * blockDim.x + threadIdx.x;
    const int total = BATCH * NQ * (CDIM / 4);
    if (i4 >= total) return;
    int c4  = i4 & 255;
    int row = i4 >> 8;
    int n   = row & (NQ - 1);
    int b   = row >> 11;
    float4 v;
    if (n == 0) v = ((const float4*)g)[c4];
    else        v = ((const float4*)x)[((size_t)(b * SEQ + n - 1)) * 256 + c4];
    v.x = __uint_as_float(f2tf32f(v.x));
    v.y = __uint_as_float(f2tf32f(v.y));
    v.z = __uint_as_float(f2tf32f(v.z));
    v.w = __uint_as_float(f2tf32f(v.w));
    ((float4*)d_xg)[i4] = v;
}

// ============ tf32 mma.sync GEMM: C = A @ W^T (+bias/epilogue) ==============
// Operands are PRE-ROUNDED to tf32 — no cvt in the mainloop.
// EPI=0: C[row*Nn+col] = tf32_round(acc)   (feeds the next tf32 stage)
// EPI=1: concat-drop + bias, full fp32 store (final output)
#define GSTAGES 3
#define GSTAGE_BYTES 32768
#define GEMM_SMEM_TOTAL (GSTAGES * GSTAGE_BYTES)   // 96 KB

template<int EPI>
__global__ void __launch_bounds__(256)
bwa_mma_gemm(const float* __restrict__ A, const float* __restrict__ W,
             float* __restrict__ C, int Nn, int K,
             const float* __restrict__ bias)
{
    extern __shared__ __align__(1024) char smem[];
    const uint32_t sb = smem_u32(smem);
    const int tid  = threadIdx.x;
    const int wid  = tid >> 5;
    const int lane = tid & 31;
    const int wm   = wid >> 1;
    const int wn   = wid & 1;
    const int m0   = blockIdx.y * 128;
    const int n0   = blockIdx.x * 128;

    const float* Abase = A + (size_t)m0 * K;
    const float* Wbase = W + (size_t)n0 * K;

    uint32_t dstoff[4];
    const float* srcA[4];
    const float* srcW[4];
    #pragma unroll
    for (int j = 0; j < 4; j++) {
        int i   = tid + 256 * j;
        int row = i >> 3;
        int c   = i & 7;
        dstoff[j] = swz((uint32_t)(row * 128 + c * 16));
        srcA[j] = Abase + (size_t)row * K + c * 4;
        srcW[j] = Wbase + (size_t)row * K + c * 4;
    }

    const int nch = K >> 5;
    #pragma unroll
    for (int pc = 0; pc < 2; pc++) {
        uint32_t sA = sb + pc * GSTAGE_BYTES;
        uint32_t sB = sA + 16384;
        #pragma unroll
        for (int j = 0; j < 4; j++) {
            CP_ASYNC16(sA + dstoff[j], srcA[j] + pc * 32);
            CP_ASYNC16(sB + dstoff[j], srcW[j] + pc * 32);
        }
        CP_COMMIT();
    }

    float acc[2][8][4];
    #pragma unroll
    for (int mt = 0; mt < 2; mt++)
        #pragma unroll
        for (int j = 0; j < 8; j++)
            #pragma unroll
            for (int q = 0; q < 4; q++) acc[mt][j][q] = 0.f;

    const uint32_t lrow = (uint32_t)(lane & 15);
    const uint32_t lcol = (uint32_t)((lane >> 4) << 4);

    for (int kc = 0; kc < nch; kc++) {
        CP_WAIT1();
        __syncthreads();

        const uint32_t sA = sb + (kc % GSTAGES) * GSTAGE_BYTES;
        const uint32_t sB = sA + 16384;

        #pragma unroll
        for (int ks = 0; ks < 4; ks++) {
            const uint32_t cb = (uint32_t)(ks * 32) + lcol;
            uint32_t a[2][4];
            #pragma unroll
            for (int mt = 0; mt < 2; mt++) {
                uint32_t row = (uint32_t)(wm * 32 + mt * 16) + lrow;
                ldsm_x4(a[mt][0], a[mt][1], a[mt][2], a[mt][3],
                        sA + swz(row * 128 + cb));
            }
            uint32_t br[4][4];
            #pragma unroll
            for (int bt = 0; bt < 4; bt++) {
                uint32_t row = (uint32_t)(wn * 64 + bt * 16) + lrow;
                ldsm_x4(br[bt][0], br[bt][1], br[bt][2], br[bt][3],
                        sB + swz(row * 128 + cb));
            }
            #pragma unroll
            for (int mt = 0; mt < 2; mt++)
                #pragma unroll
                for (int j = 0; j < 8; j++) {
                    uint32_t b0 = br[j >> 1][(j & 1)];
                    uint32_t b1 = br[j >> 1][2 + (j & 1)];
                    mma_tf32(acc[mt][j], a[mt], b0, b1);
                }
        }

        if (kc + 2 < nch) {
            uint32_t fA = sb + ((kc + 2) % GSTAGES) * GSTAGE_BYTES;
            uint32_t fB = fA + 16384;
            #pragma unroll
            for (int j = 0; j < 4; j++) {
                CP_ASYNC16(fA + dstoff[j], srcA[j] + (kc + 2) * 32);
                CP_ASYNC16(fB + dstoff[j], srcW[j] + (kc + 2) * 32);
            }
        }
        CP_COMMIT();
    }

    const int lrow4 = lane >> 2;
    const int lcol2 = (lane & 3) * 2;
    #pragma unroll
    for (int mt = 0; mt < 2; mt++) {
        const int rbase = m0 + wm * 32 + mt * 16 + lrow4;
        #pragma unroll
        for (int j = 0; j < 8; j++) {
            const int col = n0 + wn * 64 + j * 8 + lcol2;
            if (EPI == 0) {
                float* p0 = C + (size_t)rbase * Nn + col;
                float* p1 = C + (size_t)(rbase + 8) * Nn + col;
                *(float2*)p0 = make_float2(__uint_as_float(f2tf32f(acc[mt][j][0])),
                                           __uint_as_float(f2tf32f(acc[mt][j][1])));
                *(float2*)p1 = make_float2(__uint_as_float(f2tf32f(acc[mt][j][2])),
                                           __uint_as_float(f2tf32f(acc[mt][j][3])));
            } else {
                float2 bb = *(const float2*)(bias + col);
                int n0r = rbase & (NQ - 1), b0r = rbase >> 11;
                if (n0r > 0) {
                    float* p = C + (size_t)(b0r * SEQ + n0r - 1) * Nn + col;
                    *(float2*)p = make_float2(acc[mt][j][0] + bb.x,
                                              acc[mt][j][1] + bb.y);
                }
                int r1 = rbase + 8;
                int n1r = r1 & (NQ - 1), b1r = r1 >> 11;
                if (n1r > 0) {
                    float* p = C + (size_t)(b1r * SEQ + n1r - 1) * Nn + col;
                    *(float2*)p = make_float2(acc[mt][j][2] + bb.x,
                                              acc[mt][j][3] + bb.y);
                }
            }
        }
    }
}

// ============ block-causal flash attention, tf32 mma.sync ===================
// qkvbuf is tf32-pre-rounded: K/V smem fills are raw copies (K via cp.async).
#define ATT_SMEM_TOTAL 65536

__global__ void __launch_bounds__(128, 3)
bwa_attn_mma(const float* __restrict__ qkv, float* __restrict__ att)
{
    extern __shared__ __align__(1024) char smem[];
    const uint32_t sb = smem_u32(smem);
    const uint32_t Qs = sb;
    const uint32_t Ks = sb + 16384;
    const uint32_t Vt = sb + 32768;
    const uint32_t Ps = sb + 49152;

    const int tid  = threadIdx.x;
    const int w    = tid >> 5;
    const int lane = tid & 31;
    const int qt   = (QT_TILES - 1) - (int)blockIdx.x;  // big tiles first
    const int h    = blockIdx.y;
    const int b    = blockIdx.z;

    const long long base = (long long)b * NQ * 3 * CDIM;
    const float* qp = qkv + base + h * DHEAD;
    const float* kp = qkv + base + CDIM + h * DHEAD;
    const float* vp = qkv + base + 2 * CDIM + h * DHEAD;

    // ---- load Q tile: fold softmax scale * log2(e), re-round to tf32 ----
    const float QSC = 0.125f * 1.44269504f;
    #pragma unroll
    for (int j = 0; j < 8; j++) {
        int idx = tid + 128 * j;          // 1024 float4
        int row = idx >> 4, c4 = idx & 15;
        float4 v = *(const float4*)(qp + (long long)(qt * 64 + row) * (3 * CDIM) + c4 * 4);
        ST_S4(Qs + swz256((uint32_t)(row * 256 + c4 * 16)),
              f2tf32f(v.x * QSC), f2tf32f(v.y * QSC),
              f2tf32f(v.z * QSC), f2tf32f(v.w * QSC));
    }

    float o[8][4];
    #pragma unroll
    for (int nt = 0; nt < 8; nt++)
        #pragma unroll
        for (int q = 0; q < 4; q++) o[nt][q] = 0.f;
    float mrow[2] = { -1e30f, -1e30f };
    float lsum[2] = { 0.f, 0.f };

    const uint32_t lr = (uint32_t)(lane & 15);
    const uint32_t lc = (uint32_t)((lane >> 4) << 4);
    const uint32_t arow = (uint32_t)(16 * w) + lr;

    for (int kt = 0; kt <= qt; kt++) {
        __syncthreads();   // previous iteration finished reading Ks/Vt

        // ---- K tile [key][d]: raw cp.async copy (pre-rounded tf32) ----
        #pragma unroll
        for (int j = 0; j < 8; j++) {
            int idx = tid + 128 * j;
            int row = idx >> 4, c4 = idx & 15;
            CP_ASYNC16(Ks + swz256((uint32_t)(row * 256 + c4 * 16)),
                       kp + (long long)(kt * 64 + row) * (3 * CDIM) + c4 * 4);
        }
        CP_COMMIT();

        // ---- V tile transposed -> Vt[d][key] (raw bits) ----
        {
            int key = tid >> 1;
            int db  = (tid & 1) * 32;
            const float* src = vp + (long long)(kt * 64 + key) * (3 * CDIM) + db;
            #pragma unroll
            for (int j = 0; j < 8; j++) {
                float4 v = *(const float4*)(src + 4 * j);
                int d0 = db + 4 * j;
                ST_S1(Vt + swz256((uint32_t)((d0 + 0) * 256 + key * 4)), __float_as_uint(v.x));
                ST_S1(Vt + swz256((uint32_t)((d0 + 1) * 256 + key * 4)), __float_as_uint(v.y));
                ST_S1(Vt + swz256((uint32_t)((d0 + 2) * 256 + key * 4)), __float_as_uint(v.z));
                ST_S1(Vt + swz256((uint32_t)((d0 + 3) * 256 + key * 4)), __float_as_uint(v.w));
            }
        }
        CP_WAIT0();
        __syncthreads();

        // ---- S = Q @ K^T ----
        float s[8][4];
        #pragma unroll
        for (int nt = 0; nt < 8; nt++)
            #pragma unroll
            for (int q = 0; q < 4; q++) s[nt][q] = 0.f;

        #pragma unroll
        for (int ks = 0; ks < 8; ks++) {
            const uint32_t cb = (uint32_t)(32 * ks) + lc;
            uint32_t a[4];
            ldsm_x4(a[0], a[1], a[2], a[3], Qs + swz256(arow * 256 + cb));
            uint32_t br[4][4];
            #pragma unroll
            for (int bt = 0; bt < 4; bt++)
                ldsm_x4(br[bt][0], br[bt][1], br[bt][2], br[bt][3],
                        Ks + swz256(((uint32_t)(16 * bt) + lr) * 256 + cb));
            #pragma unroll
            for (int nt = 0; nt < 8; nt++)
                mma_tf32(s[nt], a, br[nt >> 1][nt & 1], br[nt >> 1][2 + (nt & 1)]);
        }

        // ---- online softmax (base-2 domain) ----
        float rm0 = -1e30f, rm1 = -1e30f;
        #pragma unroll
        for (int nt = 0; nt < 8; nt++) {
            rm0 = fmaxf(rm0, fmaxf(s[nt][0], s[nt][1]));
            rm1 = fmaxf(rm1, fmaxf(s[nt][2], s[nt][3]));
        }
        rm0 = fmaxf(rm0, __shfl_xor_sync(0xffffffffu, rm0, 1));
        rm0 = fmaxf(rm0, __shfl_xor_sync(0xffffffffu, rm0, 2));
        rm1 = fmaxf(rm1, __shfl_xor_sync(0xffffffffu, rm1, 1));
        rm1 = fmaxf(rm1, __shfl_xor_sync(0xffffffffu, rm1, 2));

        float mn0 = fmaxf(mrow[0], rm0), mn1 = fmaxf(mrow[1], rm1);
        float al0 = ex2(mrow[0] - mn0),  al1 = ex2(mrow[1] - mn1);
        mrow[0] = mn0; mrow[1] = mn1;

        float rs0 = 0.f, rs1 = 0.f;
        #pragma unroll
        for (int nt = 0; nt < 8; nt++) {
            s[nt][0] = ex2(s[nt][0] - mn0);
            s[nt][1] = ex2(s[nt][1] - mn0);
            s[nt][2] = ex2(s[nt][2] - mn1);
            s[nt][3] = ex2(s[nt][3] - mn1);
            rs0 += s[nt][0] + s[nt][1];
            rs1 += s[nt][2] + s[nt][3];
        }
        rs0 += __shfl_xor_sync(0xffffffffu, rs0, 1);
        rs0 += __shfl_xor_sync(0xffffffffu, rs0, 2);
        rs1 += __shfl_xor_sync(0xffffffffu, rs1, 1);
        rs1 += __shfl_xor_sync(0xffffffffu, rs1, 2);
        lsum[0] = lsum[0] * al0 + rs0;
        lsum[1] = lsum[1] * al1 + rs1;
        #pragma unroll
        for (int nt = 0; nt < 8; nt++) {
            o[nt][0] *= al0; o[nt][1] *= al0;
            o[nt][2] *= al1; o[nt][3] *= al1;
        }

        // ---- store P (tf32) to warp-private smem rows ----
        const uint32_t pr = (uint32_t)(16 * w + (lane >> 2));
        #pragma unroll
        for (int nt = 0; nt < 8; nt++) {
            uint32_t cbyte = (uint32_t)(32 * nt + 8 * (lane & 3));
            ST_S2(Ps + swz256(pr * 256 + cbyte), f2tf32f(s[nt][0]), f2tf32f(s[nt][1]));
            ST_S2(Ps + swz256((pr + 8) * 256 + cbyte), f2tf32f(s[nt][2]), f2tf32f(s[nt][3]));
        }
        __syncwarp();

        // ---- O += P @ V ----
        #pragma unroll
        for (int ks = 0; ks < 8; ks++) {
            const uint32_t cb = (uint32_t)(32 * ks) + lc;
            uint32_t a[4];
            ldsm_x4(a[0], a[1], a[2], a[3], Ps + swz256(arow * 256 + cb));
            uint32_t br[4][4];
            #pragma unroll
            for (int bt = 0; bt < 4; bt++)
                ldsm_x4(br[bt][0], br[bt][1], br[bt][2], br[bt][3],
                        Vt + swz256(((uint32_t)(16 * bt) + lr) * 256 + cb));
            #pragma unroll
            for (int nt = 0; nt < 8; nt++)
                mma_tf32(o[nt], a, br[nt >> 1][nt & 1], br[nt >> 1][2 + (nt & 1)]);
        }
        __syncwarp();
    }

    // ---- epilogue: normalize, tf32-round (feeds proj GEMM), store ----
    float i0 = 1.f / lsum[0], i1 = 1.f / lsum[1];
    int r0 = qt * 64 + 16 * w + (lane >> 2);
    float* orow0 = att + ((long long)b * NQ + r0) * CDIM + h * DHEAD;
    float* orow1 = orow0 + 8 * CDIM;
    #pragma unroll
    for (int nt = 0; nt < 8; nt++) {
        int col = 8 * nt + 2 * (lane & 3);
        *(float2*)(orow0 + col) = make_float2(__uint_as_float(f2tf32f(o[nt][0] * i0)),
                                              __uint_as_float(f2tf32f(o[nt][1] * i0)));
        *(float2*)(orow1 + col) = make_float2(__uint_as_float(f2tf32f(o[nt][2] * i1)),
                                              __uint_as_float(f2tf32f(o[nt][3] * i1)));
    }
}

// ---------------- launch ----------------------------------------------------
extern "C" void kernel_launch(void* const* d_in, const int* in_sizes, int n_in,
                              void* d_out, int out_size)
{
    const float* x      = (const float*)d_in[0];
    const float* g      = (const float*)d_in[1];
    const float* qkv_w  = (const float*)d_in[2];
    const float* proj_w = (const float*)d_in[3];
    const float* proj_b = (const float*)d_in[4];
    float* out = (float*)d_out;

    float *xg, *qkvbuf, *attbuf, *qkvw_tf, *projw_tf;
    cudaGetSymbolAddress((void**)&xg,       d_xg);
    cudaGetSymbolAddress((void**)&qkvbuf,   d_qkvbuf);
    cudaGetSymbolAddress((void**)&attbuf,   d_attbuf);
    cudaGetSymbolAddress((void**)&qkvw_tf,  d_qkvw_tf);
    cudaGetSymbolAddress((void**)&projw_tf, d_projw_tf);

    cudaFuncSetAttribute(bwa_mma_gemm<0>,
                         cudaFuncAttributeMaxDynamicSharedMemorySize, GEMM_SMEM_TOTAL);
    cudaFuncSetAttribute(bwa_mma_gemm<1>,
                         cudaFuncAttributeMaxDynamicSharedMemorySize, GEMM_SMEM_TOTAL);
    cudaFuncSetAttribute(bwa_attn_mma,
                         cudaFuncAttributeMaxDynamicSharedMemorySize, ATT_SMEM_TOTAL);

    // 0) pre-round weights to tf32
    {
        int n4 = 3 * CDIM * CDIM / 4;
        bwa_round_tf32<<<(n4 + 255) / 256, 256>>>(qkv_w, qkvw_tf, n4);
        n4 = CDIM * CDIM / 4;
        bwa_round_tf32<<<(n4 + 255) / 256, 256>>>(proj_w, projw_tf, n4);
    }
    // 1) concat global token + x (tf32-rounded)
    {
        int total4 = BATCH * NQ * (CDIM / 4);
        bwa_build_xg<<<(total4 + 255) / 256, 256>>>(x, g);
    }
    // 2) QKV GEMM (tf32 mma.sync), tf32-rounded output
    {
        dim3 grid(3 * CDIM / 128, (BATCH * NQ) / 128, 1);
        bwa_mma_gemm<0><<<grid, 256, GEMM_SMEM_TOTAL>>>(
            xg, qkvw_tf, qkvbuf, 3 * CDIM, CDIM, nullptr);
    }
    // 3) block-causal flash attention (tf32 mma.sync), tf32-rounded output
    {
        dim3 grid(QT_TILES, NHEAD, BATCH);
        bwa_attn_mma<<<grid, 128, ATT_SMEM_TOTAL>>>(qkvbuf, attbuf);
    }
    // 4) output projection with fused concat-drop + bias (fp32 store)
    {
        dim3 grid(CDIM / 128, (BATCH * NQ) / 128, 1);
        bwa_mma_gemm<1><<<grid, 256, GEMM_SMEM_TOTAL>>>(
            attbuf, projw_tf, out, CDIM, CDIM, proj_b);
    }
}

// round 7
// speedup vs baseline: 8.6899x; 2.3707x over previous
#include <cuda_runtime.h>
#include <cuda_fp16.h>
#include <cstdint>
#include <math.h>

#define BATCH  2
#define SEQ    2047
#define NQ     2048
#define CDIM   1024
#define NHEAD  16
#define DHEAD  64
#define QT_TILES 32   // NQ / 64

// ---------------- scratch (device globals: no allocations allowed) ----------
__device__ __half d_xg[(size_t)BATCH * NQ * CDIM];           // fp16 inputs
__device__ __half d_qkvbuf[(size_t)BATCH * NQ * 3 * CDIM];   // fp16 (Q pre-scaled)
__device__ __half d_attbuf[(size_t)BATCH * NQ * CDIM];       // fp16 attention out
__device__ __half d_qkvw_h[(size_t)3 * CDIM * CDIM];         // fp16 weights
__device__ __half d_projw_h[(size_t)CDIM * CDIM];

// ======================= helpers ========================
__device__ __forceinline__ uint32_t smem_u32(const void* p) {
    uint32_t a;
    asm("{ .reg .u64 t; cvta.to.shared.u64 t, %1; cvt.u32.u64 %0, t; }"
        : "=r"(a) : "l"(p));
    return a;
}
__device__ __forceinline__ float ex2(float x) {
    float r;
    asm("ex2.approx.ftz.f32 %0, %1;" : "=f"(r) : "f"(x));
    return r;
}
__device__ __forceinline__ uint32_t packh2(float lo, float hi) {
    __half2 h = __floats2half2_rn(lo, hi);
    return *(uint32_t*)&h;
}
__device__ __forceinline__ void ldsm_x4(uint32_t& r0, uint32_t& r1,
                                        uint32_t& r2, uint32_t& r3, uint32_t addr) {
    asm volatile("ldmatrix.sync.aligned.m8n8.x4.shared.b16 {%0,%1,%2,%3}, [%4];"
                 : "=r"(r0), "=r"(r1), "=r"(r2), "=r"(r3) : "r"(addr));
}
__device__ __forceinline__ void ldsm_x4t(uint32_t& r0, uint32_t& r1,
                                         uint32_t& r2, uint32_t& r3, uint32_t addr) {
    asm volatile("ldmatrix.sync.aligned.m8n8.x4.trans.shared.b16 {%0,%1,%2,%3}, [%4];"
                 : "=r"(r0), "=r"(r1), "=r"(r2), "=r"(r3) : "r"(addr));
}
__device__ __forceinline__ void mma_f16(float* c, const uint32_t* a,
                                        uint32_t b0, uint32_t b1) {
    asm volatile(
        "mma.sync.aligned.m16n8k16.row.col.f32.f16.f16.f32 "
        "{%0,%1,%2,%3}, {%4,%5,%6,%7}, {%8,%9}, {%0,%1,%2,%3};"
        : "+f"(c[0]), "+f"(c[1]), "+f"(c[2]), "+f"(c[3])
        : "r"(a[0]), "r"(a[1]), "r"(a[2]), "r"(a[3]), "r"(b0), "r"(b1));
}
#define CP_ASYNC16(dst, src) \
    asm volatile("cp.async.cg.shared.global [%0], [%1], 16;" \
                 :: "r"(dst), "l"(src) : "memory")
#define CP_COMMIT()  asm volatile("cp.async.commit_group;" ::: "memory")
#define CP_WAIT1()   asm volatile("cp.async.wait_group 1;" ::: "memory")
#define CP_WAIT0()   asm volatile("cp.async.wait_group 0;" ::: "memory")

__device__ __forceinline__ uint32_t swz(uint32_t off) {    // 128B-row tiles
    return off ^ ((off >> 3) & 0x70);
}

// ---------------- kernel: fp32 -> fp16 weight conversion --------------------
// First qrows4 float4s get scaled by qsc (folds softmax scale * log2e into Wq).
__global__ void bwa_w2h(const float* __restrict__ src, __half* __restrict__ dst,
                        int n4, int qrows4, float qsc)
{
    int i = blockIdx.x * blockDim.x + threadIdx.x;
    if (i >= n4) return;
    float4 v = ((const float4*)src)[i];
    float s = (i < qrows4) ? qsc : 1.0f;
    ((__half2*)dst)[i * 2 + 0] = __floats2half2_rn(v.x * s, v.y * s);
    ((__half2*)dst)[i * 2 + 1] = __floats2half2_rn(v.z * s, v.w * s);
}

// ---------------- kernel 0: build xg = concat(g, x) as fp16 -----------------
__global__ void bwa_build_xg(const float* __restrict__ x,
                             const float* __restrict__ g)
{
    int i4 = blockIdx.x * blockDim.x + threadIdx.x;
    const int total = BATCH * NQ * (CDIM / 4);
    if (i4 >= total) return;
    int c4  = i4 & 255;
    int row = i4 >> 8;
    int n   = row & (NQ - 1);
    int b   = row >> 11;
    float4 v;
    if (n == 0) v = ((const float4*)g)[c4];
    else        v = ((const float4*)x)[((size_t)(b * SEQ + n - 1)) * 256 + c4];
    ((__half2*)d_xg)[i4 * 2 + 0] = __floats2half2_rn(v.x, v.y);
    ((__half2*)d_xg)[i4 * 2 + 1] = __floats2half2_rn(v.z, v.w);
}

// ============ fp16 mma.sync GEMM: C = A @ W^T (+bias/epilogue) ==============
// A: [M, K] half, W: [Nn, K] half. CTA tile 128x128, K chunks of 64.
// EPI=0: C is half*, plain half2 store.
// EPI=1: C is float*, concat-drop + bias epilogue.
#define GSTAGES 3
#define GSTAGE_BYTES 32768                          // A 16KB + B 16KB
#define GEMM_SMEM_TOTAL (GSTAGES * GSTAGE_BYTES)    // 96 KB

template<int EPI>
__global__ void __launch_bounds__(256)
bwa_mma_gemm(const __half* __restrict__ A, const __half* __restrict__ W,
             void* __restrict__ Cv, int Nn, int K,
             const float* __restrict__ bias)
{
    extern __shared__ __align__(1024) char smem[];
    const uint32_t sb = smem_u32(smem);
    const int tid  = threadIdx.x;
    const int wid  = tid >> 5;
    const int lane = tid & 31;
    const int wm   = wid >> 1;       // 0..3 -> m offset 32*wm
    const int wn   = wid & 1;        // 0..1 -> n offset 64*wn
    const int m0   = blockIdx.y * 128;
    const int n0   = blockIdx.x * 128;

    const __half* Abase = A + (size_t)m0 * K;
    const __half* Wbase = W + (size_t)n0 * K;

    // 1024 16B-transfers per 128x64-half tile; 4 per thread per tile
    uint32_t dstoff[4];
    const __half* srcA[4];
    const __half* srcW[4];
    #pragma unroll
    for (int j = 0; j < 4; j++) {
        int i   = tid + 256 * j;
        int row = i >> 3;
        int c   = i & 7;
        dstoff[j] = swz((uint32_t)(row * 128 + c * 16));
        srcA[j] = Abase + (size_t)row * K + c * 8;
        srcW[j] = Wbase + (size_t)row * K + c * 8;
    }

    const int nch = K >> 6;          // K/64 = 16
    #pragma unroll
    for (int pc = 0; pc < 2; pc++) {
        uint32_t sA = sb + pc * GSTAGE_BYTES;
        uint32_t sB = sA + 16384;
        #pragma unroll
        for (int j = 0; j < 4; j++) {
            CP_ASYNC16(sA + dstoff[j], srcA[j] + pc * 64);
            CP_ASYNC16(sB + dstoff[j], srcW[j] + pc * 64);
        }
        CP_COMMIT();
    }

    float acc[2][8][4];
    #pragma unroll
    for (int mt = 0; mt < 2; mt++)
        #pragma unroll
        for (int j = 0; j < 8; j++)
            #pragma unroll
            for (int q = 0; q < 4; q++) acc[mt][j][q] = 0.f;

    const uint32_t lr = (uint32_t)(lane & 15);
    const uint32_t lc = (uint32_t)((lane >> 4) << 4);

    for (int kc = 0; kc < nch; kc++) {
        CP_WAIT1();
        __syncthreads();

        const uint32_t sA = sb + (kc % GSTAGES) * GSTAGE_BYTES;
        const uint32_t sB = sA + 16384;

        #pragma unroll
        for (int ks = 0; ks < 4; ks++) {           // 4 x k16 per chunk
            const uint32_t cb = (uint32_t)(ks * 32) + lc;
            uint32_t a[2][4];
            #pragma unroll
            for (int mt = 0; mt < 2; mt++) {
                uint32_t row = (uint32_t)(wm * 32 + mt * 16) + lr;
                ldsm_x4(a[mt][0], a[mt][1], a[mt][2], a[mt][3],
                        sA + swz(row * 128 + cb));
            }
            uint32_t br[4][4];
            #pragma unroll
            for (int bt = 0; bt < 4; bt++) {
                uint32_t row = (uint32_t)(wn * 64 + bt * 16) + lr;
                ldsm_x4(br[bt][0], br[bt][1], br[bt][2], br[bt][3],
                        sB + swz(row * 128 + cb));
            }
            #pragma unroll
            for (int mt = 0; mt < 2; mt++)
                #pragma unroll
                for (int j = 0; j < 8; j++)
                    mma_f16(acc[mt][j], a[mt],
                            br[j >> 1][j & 1], br[j >> 1][2 + (j & 1)]);
        }

        if (kc + 2 < nch) {
            uint32_t fA = sb + ((kc + 2) % GSTAGES) * GSTAGE_BYTES;
            uint32_t fB = fA + 16384;
            #pragma unroll
            for (int j = 0; j < 4; j++) {
                CP_ASYNC16(fA + dstoff[j], srcA[j] + (kc + 2) * 64);
                CP_ASYNC16(fB + dstoff[j], srcW[j] + (kc + 2) * 64);
            }
        }
        CP_COMMIT();
    }

    const int lrow4 = lane >> 2;
    const int lcol2 = (lane & 3) * 2;
    #pragma unroll
    for (int mt = 0; mt < 2; mt++) {
        const int rbase = m0 + wm * 32 + mt * 16 + lrow4;
        #pragma unroll
        for (int j = 0; j < 8; j++) {
            const int col = n0 + wn * 64 + j * 8 + lcol2;
            if (EPI == 0) {
                __half* Ch = (__half*)Cv;
                *(__half2*)(Ch + (size_t)rbase * Nn + col) =
                    __floats2half2_rn(acc[mt][j][0], acc[mt][j][1]);
                *(__half2*)(Ch + (size_t)(rbase + 8) * Nn + col) =
                    __floats2half2_rn(acc[mt][j][2], acc[mt][j][3]);
            } else {
                float* C = (float*)Cv;
                float2 bb = *(const float2*)(bias + col);
                int n0r = rbase & (NQ - 1), b0r = rbase >> 11;
                if (n0r > 0) {
                    float* p = C + (size_t)(b0r * SEQ + n0r - 1) * Nn + col;
                    *(float2*)p = make_float2(acc[mt][j][0] + bb.x,
                                              acc[mt][j][1] + bb.y);
                }
                int r1 = rbase + 8;
                int n1r = r1 & (NQ - 1), b1r = r1 >> 11;
                if (n1r > 0) {
                    float* p = C + (size_t)(b1r * SEQ + n1r - 1) * Nn + col;
                    *(float2*)p = make_float2(acc[mt][j][2] + bb.x,
                                              acc[mt][j][3] + bb.y);
                }
            }
        }
    }
}

// ============ block-causal flash attention, fp16 mma.sync ===================
// CTA = (b, h, qt): 64 queries, 4 warps (16 rows each). Q fragments preloaded;
// K/V double-buffered cp.async; P stays in registers; V via ldmatrix.trans.
// smem: Q 8KB + 2 stages x (K 8KB + V 8KB) = 40 KB.
#define ATT_SMEM_TOTAL 40960

__global__ void __launch_bounds__(128, 4)
bwa_attn_mma(const __half* __restrict__ qkv, __half* __restrict__ att)
{
    extern __shared__ __align__(1024) char smem[];
    const uint32_t sb = smem_u32(smem);
    const uint32_t Qs = sb;

    const int tid  = threadIdx.x;
    const int w    = tid >> 5;
    const int lane = tid & 31;
    const int qt   = (QT_TILES - 1) - (int)blockIdx.x;  // big tiles first
    const int h    = blockIdx.y;
    const int b    = blockIdx.z;

    const long long base = (long long)b * NQ * 3 * CDIM;
    const __half* qp = qkv + base + h * DHEAD;
    const __half* kp = qkv + base + CDIM + h * DHEAD;
    const __half* vp = qkv + base + 2 * CDIM + h * DHEAD;

    // per-thread tile-copy coords: 512 x 16B per 64x64-half tile, 4 per thread
    const int crow[4] = { tid >> 3, (tid + 128) >> 3, (tid + 256) >> 3, (tid + 384) >> 3 };
    const int ccol    = (tid & 7) * 8;              // halfs
    uint32_t  coff[4];
    #pragma unroll
    for (int j = 0; j < 4; j++)
        coff[j] = swz((uint32_t)(crow[j] * 128 + (tid & 7) * 16));

    // ---- Q tile (pre-scaled at QKV GEMM via folded weights) ----
    #pragma unroll
    for (int j = 0; j < 4; j++)
        CP_ASYNC16(Qs + coff[j], qp + (long long)(qt * 64 + crow[j]) * (3 * CDIM) + ccol);
    CP_COMMIT();

    // ---- K/V stage 0 ----
    {
        uint32_t Ks = sb + 8192, Vs = sb + 16384;
        #pragma unroll
        for (int j = 0; j < 4; j++) {
            CP_ASYNC16(Ks + coff[j], kp + (long long)crow[j] * (3 * CDIM) + ccol);
            CP_ASYNC16(Vs + coff[j], vp + (long long)crow[j] * (3 * CDIM) + ccol);
        }
        CP_COMMIT();
    }

    float o[8][4];
    #pragma unroll
    for (int nt = 0; nt < 8; nt++)
        #pragma unroll
        for (int q = 0; q < 4; q++) o[nt][q] = 0.f;
    float mrow[2] = { -1e30f, -1e30f };
    float lsum[2] = { 0.f, 0.f };

    const uint32_t lr = (uint32_t)(lane & 15);
    const uint32_t lc = (uint32_t)((lane >> 4) << 4);
    uint32_t qf[4][4];

    for (int kt = 0; kt <= qt; kt++) {
        // prefetch next K/V stage
        if (kt < qt) {
            uint32_t Ks = sb + 8192 + ((kt + 1) & 1) * 16384;
            uint32_t Vs = Ks + 8192;
            #pragma unroll
            for (int j = 0; j < 4; j++) {
                CP_ASYNC16(Ks + coff[j],
                           kp + (long long)((kt + 1) * 64 + crow[j]) * (3 * CDIM) + ccol);
                CP_ASYNC16(Vs + coff[j],
                           vp + (long long)((kt + 1) * 64 + crow[j]) * (3 * CDIM) + ccol);
            }
            CP_COMMIT();
            CP_WAIT1();
        } else {
            CP_WAIT0();
        }
        __syncthreads();

        if (kt == 0) {   // preload Q fragments once
            #pragma unroll
            for (int ks = 0; ks < 4; ks++)
                ldsm_x4(qf[ks][0], qf[ks][1], qf[ks][2], qf[ks][3],
                        Qs + swz(((uint32_t)(16 * w) + lr) * 128 + (uint32_t)(32 * ks) + lc));
        }

        const uint32_t Ks = sb + 8192 + (kt & 1) * 16384;
        const uint32_t Vs = Ks + 8192;

        // ---- S = Q @ K^T  (16 q-rows x 64 keys per warp) ----
        float s[8][4];
        #pragma unroll
        for (int nt = 0; nt < 8; nt++)
            #pragma unroll
            for (int q = 0; q < 4; q++) s[nt][q] = 0.f;

        #pragma unroll
        for (int ks = 0; ks < 4; ks++) {
            const uint32_t cb = (uint32_t)(32 * ks) + lc;
            uint32_t br[4][4];
            #pragma unroll
            for (int bt = 0; bt < 4; bt++)
                ldsm_x4(br[bt][0], br[bt][1], br[bt][2], br[bt][3],
                        Ks + swz(((uint32_t)(16 * bt) + lr) * 128 + cb));
            #pragma unroll
            for (int nt = 0; nt < 8; nt++)
                mma_f16(s[nt], qf[ks], br[nt >> 1][nt & 1], br[nt >> 1][2 + (nt & 1)]);
        }

        // ---- online softmax (base-2; scale pre-folded into Wq) ----
        float rm0 = -1e30f, rm1 = -1e30f;
        #pragma unroll
        for (int nt = 0; nt < 8; nt++) {
            rm0 = fmaxf(rm0, fmaxf(s[nt][0], s[nt][1]));
            rm1 = fmaxf(rm1, fmaxf(s[nt][2], s[nt][3]));
        }
        rm0 = fmaxf(rm0, __shfl_xor_sync(0xffffffffu, rm0, 1));
        rm0 = fmaxf(rm0, __shfl_xor_sync(0xffffffffu, rm0, 2));
        rm1 = fmaxf(rm1, __shfl_xor_sync(0xffffffffu, rm1, 1));
        rm1 = fmaxf(rm1, __shfl_xor_sync(0xffffffffu, rm1, 2));

        float mn0 = fmaxf(mrow[0], rm0), mn1 = fmaxf(mrow[1], rm1);
        float al0 = ex2(mrow[0] - mn0),  al1 = ex2(mrow[1] - mn1);
        mrow[0] = mn0; mrow[1] = mn1;

        float rs0 = 0.f, rs1 = 0.f;
        #pragma unroll
        for (int nt = 0; nt < 8; nt++) {
            s[nt][0] = ex2(s[nt][0] - mn0);
            s[nt][1] = ex2(s[nt][1] - mn0);
            s[nt][2] = ex2(s[nt][2] - mn1);
            s[nt][3] = ex2(s[nt][3] - mn1);
            rs0 += s[nt][0] + s[nt][1];
            rs1 += s[nt][2] + s[nt][3];
        }
        rs0 += __shfl_xor_sync(0xffffffffu, rs0, 1);
        rs0 += __shfl_xor_sync(0xffffffffu, rs0, 2);
        rs1 += __shfl_xor_sync(0xffffffffu, rs1, 1);
        rs1 += __shfl_xor_sync(0xffffffffu, rs1, 2);
        lsum[0] = lsum[0] * al0 + rs0;
        lsum[1] = lsum[1] * al1 + rs1;
        #pragma unroll
        for (int nt = 0; nt < 8; nt++) {
            o[nt][0] *= al0; o[nt][1] *= al0;
            o[nt][2] *= al1; o[nt][3] *= al1;
        }

        // ---- pack P into A-fragments (registers only) ----
        uint32_t pa[4][4];
        #pragma unroll
        for (int j = 0; j < 4; j++) {
            pa[j][0] = packh2(s[2 * j][0],     s[2 * j][1]);
            pa[j][1] = packh2(s[2 * j][2],     s[2 * j][3]);
            pa[j][2] = packh2(s[2 * j + 1][0], s[2 * j + 1][1]);
            pa[j][3] = packh2(s[2 * j + 1][2], s[2 * j + 1][3]);
        }

        // ---- O += P @ V  (V^T fragments via ldmatrix.trans) ----
        #pragma unroll
        for (int j = 0; j < 4; j++) {             // key16 groups
            uint32_t bv[4][4];
            #pragma unroll
            for (int dt = 0; dt < 4; dt++)        // d16 tiles
                ldsm_x4t(bv[dt][0], bv[dt][1], bv[dt][2], bv[dt][3],
                         Vs + swz(((uint32_t)(16 * j) + lr) * 128
                                  + (uint32_t)(32 * dt) + lc));
            #pragma unroll
            for (int nt = 0; nt < 8; nt++)
                mma_f16(o[nt], pa[j],
                        bv[nt >> 1][(nt & 1) * 2], bv[nt >> 1][(nt & 1) * 2 + 1]);
        }
        __syncthreads();   // all warps done with this stage before it is refilled
    }

    // ---- epilogue: normalize, store fp16 ----
    float i0 = 1.f / lsum[0], i1 = 1.f / lsum[1];
    int r0 = qt * 64 + 16 * w + (lane >> 2);
    __half* orow0 = att + ((long long)b * NQ + r0) * CDIM + h * DHEAD;
    __half* orow1 = orow0 + 8 * CDIM;
    #pragma unroll
    for (int nt = 0; nt < 8; nt++) {
        int col = 8 * nt + 2 * (lane & 3);
        *(__half2*)(orow0 + col) = __floats2half2_rn(o[nt][0] * i0, o[nt][1] * i0);
        *(__half2*)(orow1 + col) = __floats2half2_rn(o[nt][2] * i1, o[nt][3] * i1);
    }
}

// ---------------- launch ----------------------------------------------------
extern "C" void kernel_launch(void* const* d_in, const int* in_sizes, int n_in,
                              void* d_out, int out_size)
{
    const float* x      = (const float*)d_in[0];
    const float* g      = (const float*)d_in[1];
    const float* qkv_w  = (const float*)d_in[2];
    const float* proj_w = (const float*)d_in[3];
    const float* proj_b = (const float*)d_in[4];
    float* out = (float*)d_out;

    __half *xg, *qkvbuf, *attbuf, *qkvw_h, *projw_h;
    cudaGetSymbolAddress((void**)&xg,      d_xg);
    cudaGetSymbolAddress((void**)&qkvbuf,  d_qkvbuf);
    cudaGetSymbolAddress((void**)&attbuf,  d_attbuf);
    cudaGetSymbolAddress((void**)&qkvw_h,  d_qkvw_h);
    cudaGetSymbolAddress((void**)&projw_h, d_projw_h);

    cudaFuncSetAttribute(bwa_mma_gemm<0>,
                         cudaFuncAttributeMaxDynamicSharedMemorySize, GEMM_SMEM_TOTAL);
    cudaFuncSetAttribute(bwa_mma_gemm<1>,
                         cudaFuncAttributeMaxDynamicSharedMemorySize, GEMM_SMEM_TOTAL);
    cudaFuncSetAttribute(bwa_attn_mma,
                         cudaFuncAttributeMaxDynamicSharedMemorySize, ATT_SMEM_TOTAL);

    const float QSC = 0.125f * 1.44269504f;   // softmax scale * log2(e)

    // 0) convert weights to fp16 (Q weight rows pre-scaled)
    {
        int n4 = 3 * CDIM * CDIM / 4;
        int qrows4 = CDIM * CDIM / 4;          // first 1024 rows = Wq
        bwa_w2h<<<(n4 + 255) / 256, 256>>>(qkv_w, qkvw_h, n4, qrows4, QSC);
        n4 = CDIM * CDIM / 4;
        bwa_w2h<<<(n4 + 255) / 256, 256>>>(proj_w, projw_h, n4, 0, 1.0f);
    }
    // 1) concat global token + x (fp16)
    {
        int total4 = BATCH * NQ * (CDIM / 4);
        bwa_build_xg<<<(total4 + 255) / 256, 256>>>(x, g);
    }
    // 2) QKV GEMM (fp16 mma m16n8k16)
    {
        dim3 grid(3 * CDIM / 128, (BATCH * NQ) / 128, 1);
        bwa_mma_gemm<0><<<grid, 256, GEMM_SMEM_TOTAL>>>(
            xg, qkvw_h, qkvbuf, 3 * CDIM, CDIM, nullptr);
    }
    // 3) block-causal flash attention (fp16, register-resident P)
    {
        dim3 grid(QT_TILES, NHEAD, BATCH);
        bwa_attn_mma<<<grid, 128, ATT_SMEM_TOTAL>>>(qkvbuf, attbuf);
    }
    // 4) output projection with fused concat-drop + bias (fp32 store)
    {
        dim3 grid(CDIM / 128, (BATCH * NQ) / 128, 1);
        bwa_mma_gemm<1><<<grid, 256, GEMM_SMEM_TOTAL>>>(
            attbuf, projw_h, out, CDIM, CDIM, proj_b);
    }
}